// round 11
// baseline (speedup 1.0000x reference)
#include <cuda_runtime.h>
#include <cuda_fp16.h>
#include <math.h>
#include <stdint.h>

// Problem constants
#define L_DIM 4096
#define M_DIM 1024
#define P_DIM 4096
#define HID   512
#define NH    8
#define DH    64
#define HK    (NH * M_DIM)   // 8192 flattened (h, m)
#define DHALF 256
#define EPS_LN 1e-5f
#define WSQ   (HID * HID)

// ---------------- scratch (static device globals; no allocation) ----------------
__device__ float g_preL[L_DIM * DHALF];
__device__ float g_preP[P_DIM * DHALF];

// packed fp16 weights (transposed [N][K]) and packed biases
// slots: 0 Wl, 1 Wp, 2 Wm, 3 Wql, 4 Wqp, 5 Wkl, 6 Wkp, 7 Wvl, 8 Wvp
__device__ __half g_hWcat[9 * WSQ];
__device__ float  g_biascat[9 * HID];
__device__ __half g_hWmlT[DHALF * 2 * HID];   // [256][1024]
__device__ __half g_hWmpT[DHALF * 2 * HID];

// fp16 activations (L/P pairs contiguous for z-batching)
__device__ __half g_hEmb [2 * L_DIM * HID];            // Le, Pe
__device__ __half g_hMe  [M_DIM * HID];
__device__ __half g_hmt  [M_DIM * HID];
__device__ __half g_hltpt[2 * L_DIM * HID];            // lt, pt
__device__ __half g_hQlp [2 * L_DIM * HID];            // Ql, Qp
__device__ __half g_hKm  [2 * M_DIM * HID];            // Kl, Kp
__device__ __half g_hVTm [2 * HID * M_DIM];            // VlT, VpT  ([HID][M])
__device__ __half g_haw  [(size_t)2 * L_DIM * HK];     // awl, awp
__device__ __half g_hawT [(size_t)2 * HK * L_DIM];     // awpT, awlT  (note p first)
__device__ __half g_hctx [2 * L_DIM * HID];            // ctxl, ctxp
__device__ __half g_hctxT[2 * HID * L_DIM];            // ctxpT, ctxlT (p first)
__device__ __half g_hTT  [2 * HID * HK];               // TpT, TlT
__device__ __half g_hfin [2 * L_DIM * HID];            // finl, finp

// ================= fp16 tensor-core GEMM (mma.sync NT, 3-stage, strided/batched) =================
// C[M,N] = alpha * A[M,K](f16, ld=lda) @ B[N,K](f16, ld=ldb)^T  (+bias) (+Cadd) (relu)
// WTN: warp tile N (32). CADDM: 0 none, 1 f32 Cadd, 2 f16 Cadd.
// BIASM: 0 none, 1 per-col, 2 per-row.
// DUALA: A supplies K rows [0,Kd/2) and A2 supplies [Kd/2,Kd) (both ld=lda).
// Requires M%128==0, N%BN==0, K%32==0, K>=64 (all call sites exact).
#define HPAD 40

__device__ __forceinline__ uint32_t smem_u32(const void* p) {
    return (uint32_t)__cvta_generic_to_shared(p);
}

template<int BN, int WTN, bool RELU, int CADDM, bool OUTF16, int BIASM, bool DUALA>
__global__ void __launch_bounds__(256)
hgemm_k(const __half* __restrict__ A, const __half* __restrict__ A2, int lda, long sA,
        const __half* __restrict__ B, int ldb, long sB,
        float* __restrict__ C, __half* __restrict__ Ch, int ldc, long sC,
        const float* __restrict__ CaddF, const __half* __restrict__ CaddH,
        int ldadd, long sAdd,
        const float* __restrict__ bias, long sBias,
        float alpha, int Md, int Nd, int Kd)
{
    constexpr int BM = 128;
    constexpr int WN = BN / WTN;         // warps along N
    constexpr int WM = 8 / WN;           // warps along M
    constexpr int MI = BM / (WM * 16);   // m16 fragments per warp
    constexpr int NI = WTN / 8;          // n8 fragments per warp

    extern __shared__ __half hsm[];
    __half* sAb = hsm;                   // 3 stages x BM*HPAD
    __half* sBb = hsm + 3 * BM * HPAD;   // 3 stages x BN*HPAD

    const int tid  = threadIdx.x;
    const int wid  = tid >> 5, lane = tid & 31;
    const int wr   = wid / WN, wc = wid % WN;
    const int m0   = blockIdx.y * BM;
    const int n0   = blockIdx.x * BN;
    const long z   = blockIdx.z;

    A += z * sA;
    B += z * sB;

    float acc[MI][NI][4];
#pragma unroll
    for (int mi = 0; mi < MI; mi++)
#pragma unroll
        for (int ni = 0; ni < NI; ni++)
#pragma unroll
            for (int q = 0; q < 4; q++) acc[mi][ni][q] = 0.f;

    const int KT  = Kd / 32;
    const int KTH = Kd / 64;             // DUALA switch point

    auto load_stage = [&](int s, int kt) {
        __half* sa = sAb + s * BM * HPAD;
        __half* sb = sBb + s * BN * HPAD;
        const __half* Ause = A;
        int ktA = kt;
        if (DUALA && kt >= KTH) { Ause = A2; ktA = kt - KTH; }
#pragma unroll
        for (int i = 0; i < (BM * 4) / 256; i++) {
            int idx = tid + i * 256;
            int r = idx >> 2, u = idx & 3;
            const __half* g = Ause + (size_t)(m0 + r) * lda + ktA * 32 + u * 8;
            asm volatile("cp.async.ca.shared.global [%0], [%1], 16;\n"
                         :: "r"(smem_u32(&sa[r * HPAD + u * 8])), "l"(g));
        }
#pragma unroll
        for (int i = 0; i < (BN * 4) / 256; i++) {
            int idx = tid + i * 256;
            int r = idx >> 2, u = idx & 3;
            const __half* g = B + (size_t)(n0 + r) * ldb + kt * 32 + u * 8;
            asm volatile("cp.async.ca.shared.global [%0], [%1], 16;\n"
                         :: "r"(smem_u32(&sb[r * HPAD + u * 8])), "l"(g));
        }
        asm volatile("cp.async.commit_group;\n");
    };

    load_stage(0, 0);
    load_stage(1, 1);        // KT >= 2 at every call site

    for (int kt = 0; kt < KT; kt++) {
        const int s = kt % 3;
        if (kt + 1 < KT) { asm volatile("cp.async.wait_group 1;\n" ::: "memory"); }
        else             { asm volatile("cp.async.wait_group 0;\n" ::: "memory"); }
        __syncthreads();
        if (kt + 2 < KT) load_stage((kt + 2) % 3, kt + 2);

        const __half* sa = sAb + s * BM * HPAD;
        const __half* sb = sBb + s * BN * HPAD;

#pragma unroll
        for (int ks = 0; ks < 2; ks++) {
            uint32_t a[MI][4], b[NI][2];
#pragma unroll
            for (int mi = 0; mi < MI; mi++) {
                int row = wr * (MI * 16) + mi * 16 + (lane & 15);
                int col = ks * 16 + (lane >> 4) * 8;
                uint32_t addr = smem_u32(&sa[row * HPAD + col]);
                asm volatile("ldmatrix.sync.aligned.m8n8.x4.shared.b16 {%0,%1,%2,%3}, [%4];\n"
                             : "=r"(a[mi][0]), "=r"(a[mi][1]), "=r"(a[mi][2]), "=r"(a[mi][3])
                             : "r"(addr));
            }
#pragma unroll
            for (int j = 0; j < NI / 2; j++) {
                int n   = wc * WTN + j * 16 + (lane & 7) + ((lane >> 4) << 3);
                int col = ks * 16 + ((lane >> 3) & 1) * 8;
                uint32_t addr = smem_u32(&sb[n * HPAD + col]);
                uint32_t r0, r1, r2, r3;
                asm volatile("ldmatrix.sync.aligned.m8n8.x4.shared.b16 {%0,%1,%2,%3}, [%4];\n"
                             : "=r"(r0), "=r"(r1), "=r"(r2), "=r"(r3) : "r"(addr));
                b[2 * j][0] = r0; b[2 * j][1] = r1;
                b[2 * j + 1][0] = r2; b[2 * j + 1][1] = r3;
            }
#pragma unroll
            for (int mi = 0; mi < MI; mi++)
#pragma unroll
                for (int ni = 0; ni < NI; ni++)
                    asm volatile(
                        "mma.sync.aligned.m16n8k16.row.col.f32.f16.f16.f32 "
                        "{%0,%1,%2,%3}, {%4,%5,%6,%7}, {%8,%9}, {%0,%1,%2,%3};\n"
                        : "+f"(acc[mi][ni][0]), "+f"(acc[mi][ni][1]),
                          "+f"(acc[mi][ni][2]), "+f"(acc[mi][ni][3])
                        : "r"(a[mi][0]), "r"(a[mi][1]), "r"(a[mi][2]), "r"(a[mi][3]),
                          "r"(b[ni][0]), "r"(b[ni][1]));
        }
    }
    __syncthreads();

    // epilogue
    const float* bz = bias + z * sBias;
#pragma unroll
    for (int mi = 0; mi < MI; mi++) {
        int row = m0 + wr * (MI * 16) + mi * 16 + (lane >> 2);
#pragma unroll
        for (int ni = 0; ni < NI; ni++) {
            int col = n0 + wc * WTN + ni * 8 + (lane & 3) * 2;
            float2 lo = make_float2(acc[mi][ni][0] * alpha, acc[mi][ni][1] * alpha);
            float2 hi = make_float2(acc[mi][ni][2] * alpha, acc[mi][ni][3] * alpha);
            if (BIASM == 1) {
                float b0 = bz[col], b1 = bz[col + 1];
                lo.x += b0; lo.y += b1; hi.x += b0; hi.y += b1;
            }
            if (BIASM == 2) {
                float br = bz[row], br8 = bz[row + 8];
                lo.x += br; lo.y += br; hi.x += br8; hi.y += br8;
            }
            if (CADDM == 1) {
                const float* ca = CaddF + z * sAdd;
                float2 c0 = *(const float2*)&ca[(size_t)row * ldadd + col];
                float2 c1 = *(const float2*)&ca[(size_t)(row + 8) * ldadd + col];
                lo.x += c0.x; lo.y += c0.y;
                hi.x += c1.x; hi.y += c1.y;
            }
            if (CADDM == 2) {
                const __half* ca = CaddH + z * sAdd;
                float2 c0 = __half22float2(*(const __half2*)&ca[(size_t)row * ldadd + col]);
                float2 c1 = __half22float2(*(const __half2*)&ca[(size_t)(row + 8) * ldadd + col]);
                lo.x += c0.x; lo.y += c0.y;
                hi.x += c1.x; hi.y += c1.y;
            }
            if (RELU) {
                lo.x = fmaxf(lo.x, 0.f); lo.y = fmaxf(lo.y, 0.f);
                hi.x = fmaxf(hi.x, 0.f); hi.y = fmaxf(hi.y, 0.f);
            }
            if (OUTF16) {
                __half* co = Ch + z * sC;
                *(__half2*)&co[(size_t)row * ldc + col]       = __floats2half2_rn(lo.x, lo.y);
                *(__half2*)&co[(size_t)(row + 8) * ldc + col] = __floats2half2_rn(hi.x, hi.y);
            } else {
                float* co = C + z * sC;
                *(float2*)&co[(size_t)row * ldc + col]       = lo;
                *(float2*)&co[(size_t)(row + 8) * ldc + col] = hi;
            }
        }
    }
}

template<int BN, int WTN, bool RELU, int CADDM, bool OUTF16, int BIASM, bool DUALA = false>
static inline void hgemm(const __half* A, const __half* A2, int lda, long sA,
                         const __half* B, int ldb, long sB,
                         float* C, __half* Ch, int ldc, long sC,
                         const float* CaddF, const __half* CaddH, int ldadd, long sAdd,
                         const float* bias, long sBias, float alpha,
                         int Md, int Nd, int Kd, int batch)
{
    constexpr int SMEM = 3 * (128 + BN) * HPAD * 2;
    cudaFuncSetAttribute(hgemm_k<BN, WTN, RELU, CADDM, OUTF16, BIASM, DUALA>,
                         cudaFuncAttributeMaxDynamicSharedMemorySize, SMEM);
    dim3 grid(Nd / BN, Md / 128, batch);
    hgemm_k<BN, WTN, RELU, CADDM, OUTF16, BIASM, DUALA><<<grid, 256, SMEM>>>(
        A, A2, lda, sA, B, ldb, sB, C, Ch, ldc, sC, CaddF, CaddH, ldadd, sAdd,
        bias, sBias, alpha, Md, Nd, Kd);
}

// ---------------- conversions ----------------
__global__ void __launch_bounds__(256)
conv_k(const float4* __restrict__ in, __half2* __restrict__ out, int n4)
{
    int i = blockIdx.x * 256 + threadIdx.x;
    if (i < n4) {
        float4 v = in[i];
        out[2 * i]     = __floats2half2_rn(v.x, v.y);
        out[2 * i + 1] = __floats2half2_rn(v.z, v.w);
    }
}

// out[C][R] (f16) = transpose of in[R][C] (f32). R,C multiples of 32.
__global__ void __launch_bounds__(256)
tconv_f2h_k(const float* __restrict__ in, __half* __restrict__ out, int R, int C)
{
    __shared__ float t[32][33];
    int c0 = blockIdx.x * 32, r0 = blockIdx.y * 32;
    int x = threadIdx.x & 31, y = threadIdx.x >> 5;
#pragma unroll
    for (int j = 0; j < 32; j += 8)
        t[y + j][x] = in[(size_t)(r0 + y + j) * C + c0 + x];
    __syncthreads();
#pragma unroll
    for (int j = 0; j < 32; j += 8)
        out[(size_t)(c0 + y + j) * R + r0 + x] = __float2half(t[x][y + j]);
}

// out[C][R] (f16) = transpose of in[R][C] (f16). R,C multiples of 64.
// 64x64 tiles, half2 coalesced on both global sides.
__global__ void __launch_bounds__(256)
tconv_h2h64_k(const __half* __restrict__ in, __half* __restrict__ out, int R, int C)
{
    __shared__ __half t[64][65];
    const int c0 = blockIdx.x * 64, r0 = blockIdx.y * 64;
    const int x = threadIdx.x & 31;          // half2 index along the 64-wide dim
    const int y = threadIdx.x >> 5;          // 0..7

    // load: rows r0..r0+63, 32 half2 per row (coalesced 128B per warp)
#pragma unroll
    for (int j = 0; j < 64; j += 8) {
        int row = y + j;
        __half2 v = *(const __half2*)&in[(size_t)(r0 + row) * C + c0 + 2 * x];
        t[row][2 * x]     = __low2half(v);
        t[row][2 * x + 1] = __high2half(v);
    }
    __syncthreads();

    // store: out rows c0..c0+63, half2 along r (coalesced 128B per warp)
#pragma unroll
    for (int j = 0; j < 64; j += 8) {
        int col = y + j;
        __half2 v = __halves2half2(t[2 * x][col], t[2 * x + 1][col]);
        *(__half2*)&out[(size_t)(c0 + col) * R + r0 + 2 * x] = v;
    }
}

// pack 9 bias vectors (512 each) into one contiguous buffer
__global__ void __launch_bounds__(512)
pack_bias_k(float* __restrict__ dst,
            const float* b0, const float* b1, const float* b2,
            const float* b3, const float* b4, const float* b5,
            const float* b6, const float* b7, const float* b8)
{
    int t = threadIdx.x;
    dst[0 * HID + t] = b0[t];
    dst[1 * HID + t] = b1[t];
    dst[2 * HID + t] = b2[t];
    dst[3 * HID + t] = b3[t];
    dst[4 * HID + t] = b4[t];
    dst[5 * HID + t] = b5[t];
    dst[6 * HID + t] = b6[t];
    dst[7 * HID + t] = b7[t];
    dst[8 * HID + t] = b8[t];
}

// ---------------- reductions ----------------
__device__ __forceinline__ float warpRedMax(float v) {
#pragma unroll
    for (int o = 16; o > 0; o >>= 1) v = fmaxf(v, __shfl_xor_sync(0xffffffffu, v, o));
    return v;
}
__device__ __forceinline__ float warpRedSum(float v) {
#pragma unroll
    for (int o = 16; o > 0; o >>= 1) v += __shfl_xor_sync(0xffffffffu, v, o);
    return v;
}
__device__ __forceinline__ float blockMax256(float v, float* red) {
    int lane = threadIdx.x & 31, w = threadIdx.x >> 5;
    v = warpRedMax(v);
    if (lane == 0) red[w] = v;
    __syncthreads();
    float r = red[0];
#pragma unroll
    for (int i = 1; i < 8; i++) r = fmaxf(r, red[i]);
    __syncthreads();
    return r;
}
__device__ __forceinline__ float blockSum256(float v, float* red) {
    int lane = threadIdx.x & 31, w = threadIdx.x >> 5;
    v = warpRedSum(v);
    if (lane == 0) red[w] = v;
    __syncthreads();
    float r = 0.f;
#pragma unroll
    for (int i = 0; i < 8; i++) r += red[i];
    __syncthreads();
    return r;
}

// ---------------- masked softmax, in place on fp16 scores (half2-vectorized) ----------------
__global__ void __launch_bounds__(256)
softmax16_k(__half* __restrict__ S, const int* __restrict__ mask)
{
    __shared__ float red[8];
    const int l = blockIdx.x, h = blockIdx.y;
    __half2* row2 = (__half2*)(S + (size_t)l * HK + (size_t)h * M_DIM);
    const int2* m2 = (const int2*)(mask + (size_t)l * M_DIM);
    const int t = threadIdx.x;

    float2 v[2];
    float mx = -3.4e38f;
#pragma unroll
    for (int i = 0; i < 2; i++) {
        int m = t + i * 256;
        float2 f = __half22float2(row2[m]);
        int2  mm = m2[m];
        f.x = (mm.x != 0) ? f.x : -1e9f;
        f.y = (mm.y != 0) ? f.y : -1e9f;
        v[i] = f;
        mx = fmaxf(mx, fmaxf(f.x, f.y));
    }
    mx = blockMax256(mx, red);
    float sum = 0.f;
#pragma unroll
    for (int i = 0; i < 2; i++) {
        v[i].x = __expf(v[i].x - mx);
        v[i].y = __expf(v[i].y - mx);
        sum += v[i].x + v[i].y;
    }
    sum = blockSum256(sum, red);
    float inv = __frcp_rn(sum);
#pragma unroll
    for (int i = 0; i < 2; i++)
        row2[t + i * 256] = __floats2half2_rn(v[i].x * inv, v[i].y * inv);
}

// ---------------- layernorm ----------------
__global__ void __launch_bounds__(256)
ln_k(const float* __restrict__ x, const float* __restrict__ g, const float* __restrict__ be,
     float* __restrict__ out)
{
    __shared__ float red[8];
    const int r = blockIdx.x, t = threadIdx.x;
    float v = x[r * 256 + t];
    float mean = blockSum256(v, red) * (1.f / 256.f);
    float d = v - mean;
    float var = blockSum256(d * d, red) * (1.f / 256.f);
    out[r * 256 + t] = d * rsqrtf(var + EPS_LN) * g[t] + be[t];
}

// ---------------- launch ----------------
static inline void* symraw(const void* s) {
    void* p = nullptr;
    cudaGetSymbolAddress(&p, s);
    return p;
}

extern "C" void kernel_launch(void* const* d_in, const int* in_sizes, int n_in,
                              void* d_out, int out_size)
{
    (void)in_sizes; (void)n_in; (void)out_size;
    const float* Le    = (const float*)d_in[0];
    const float* Me    = (const float*)d_in[1];
    const float* Pe    = (const float*)d_in[2];
    const int*   maskL = (const int*)  d_in[3];
    const int*   maskP = (const int*)  d_in[4];
    const float *Wl  = (const float*)d_in[5],  *bl  = (const float*)d_in[6];
    const float *Wm  = (const float*)d_in[7],  *bm  = (const float*)d_in[8];
    const float *Wp  = (const float*)d_in[9],  *bp  = (const float*)d_in[10];
    const float *Wql = (const float*)d_in[11], *bql = (const float*)d_in[12];
    const float *Wkl = (const float*)d_in[13], *bkl = (const float*)d_in[14];
    const float *Wvl = (const float*)d_in[15], *bvl = (const float*)d_in[16];
    const float *Wqp = (const float*)d_in[17], *bqp = (const float*)d_in[18];
    const float *Wkp = (const float*)d_in[19], *bkp = (const float*)d_in[20];
    const float *Wvp = (const float*)d_in[21], *bvp = (const float*)d_in[22];
    const float *Wml = (const float*)d_in[23], *bml = (const float*)d_in[24];
    const float *Wmp = (const float*)d_in[25], *bmp = (const float*)d_in[26];
    const float *g1  = (const float*)d_in[27], *be1 = (const float*)d_in[28];
    const float *g2  = (const float*)d_in[29], *be2 = (const float*)d_in[30];

    float* preL = (float*)symraw(g_preL);
    float* preP = (float*)symraw(g_preP);

    __half* hWcat  = (__half*)symraw(g_hWcat);
    float*  biascat= (float*) symraw(g_biascat);
    __half* hWmlT  = (__half*)symraw(g_hWmlT);
    __half* hWmpT  = (__half*)symraw(g_hWmpT);

    __half* hEmb  = (__half*)symraw(g_hEmb);
    __half* hMe   = (__half*)symraw(g_hMe);
    __half* hmt   = (__half*)symraw(g_hmt);
    __half* hltpt = (__half*)symraw(g_hltpt);
    __half* hQlp  = (__half*)symraw(g_hQlp);
    __half* hKm   = (__half*)symraw(g_hKm);
    __half* hVTm  = (__half*)symraw(g_hVTm);
    __half* haw   = (__half*)symraw(g_haw);
    __half* hawT  = (__half*)symraw(g_hawT);
    __half* hctx  = (__half*)symraw(g_hctx);
    __half* hctxT = (__half*)symraw(g_hctxT);
    __half* hTT   = (__half*)symraw(g_hTT);
    __half* hfin  = (__half*)symraw(g_hfin);

    const float scale = 0.125f;   // 1/sqrt(DH)
    const float invH  = 0.125f;   // 1/H

    const long ES = (long)L_DIM * HID;     // embedding-sized stride
    const long AS = (long)L_DIM * HK;      // attention-map stride

    // 0) inputs + weights -> fp16 (weights transposed to [N][K], packed)
    conv_k<<<(L_DIM * HID / 4 + 255) / 256, 256>>>((const float4*)Le, (__half2*)hEmb, L_DIM * HID / 4);
    conv_k<<<(P_DIM * HID / 4 + 255) / 256, 256>>>((const float4*)Pe, (__half2*)(hEmb + ES), P_DIM * HID / 4);
    conv_k<<<(M_DIM * HID / 4 + 255) / 256, 256>>>((const float4*)Me, (__half2*)hMe, M_DIM * HID / 4);
    {
        dim3 gw(HID / 32, HID / 32);
        tconv_f2h_k<<<gw, 256>>>(Wl,  hWcat + 0 * WSQ, HID, HID);
        tconv_f2h_k<<<gw, 256>>>(Wp,  hWcat + 1 * WSQ, HID, HID);
        tconv_f2h_k<<<gw, 256>>>(Wm,  hWcat + 2 * WSQ, HID, HID);
        tconv_f2h_k<<<gw, 256>>>(Wql, hWcat + 3 * WSQ, HID, HID);
        tconv_f2h_k<<<gw, 256>>>(Wqp, hWcat + 4 * WSQ, HID, HID);
        tconv_f2h_k<<<gw, 256>>>(Wkl, hWcat + 5 * WSQ, HID, HID);
        tconv_f2h_k<<<gw, 256>>>(Wkp, hWcat + 6 * WSQ, HID, HID);
        tconv_f2h_k<<<gw, 256>>>(Wvl, hWcat + 7 * WSQ, HID, HID);
        tconv_f2h_k<<<gw, 256>>>(Wvp, hWcat + 8 * WSQ, HID, HID);
        dim3 gw2(DHALF / 32, 2 * HID / 32);
        tconv_f2h_k<<<gw2, 256>>>(Wml, hWmlT, 2 * HID, DHALF);
        tconv_f2h_k<<<gw2, 256>>>(Wmp, hWmpT, 2 * HID, DHALF);
    }
    pack_bias_k<<<1, 512>>>(biascat, bl, bp, bm, bql, bqp, bkl, bkp, bvl, bvp);

    // 1) {Le,Pe} @ {Wl,Wp} -> {lt,pt}   (z=2)
    hgemm<128,32,false,0,true,1>(hEmb, nullptr, HID, ES, hWcat, HID, WSQ,
                                 nullptr, hltpt, HID, ES, nullptr, nullptr, 0, 0,
                                 biascat, HID, 1.f, L_DIM, HID, HID, 2);
    // 2) Me @ Wm -> mt
    hgemm<128,32,false,0,true,1>(hMe, nullptr, HID, 0, hWcat + 2 * WSQ, HID, 0,
                                 nullptr, hmt, HID, 0, nullptr, nullptr, 0, 0,
                                 biascat + 2 * HID, 0, 1.f, M_DIM, HID, HID, 1);
    // 3) {lt,pt} @ {Wql,Wqp} -> {Ql,Qp}  (z=2)
    hgemm<128,32,false,0,true,1>(hltpt, nullptr, HID, ES, hWcat + 3 * WSQ, HID, WSQ,
                                 nullptr, hQlp, HID, ES, nullptr, nullptr, 0, 0,
                                 biascat + 3 * HID, HID, 1.f, L_DIM, HID, HID, 2);
    // 4) mt @ {Wkl,Wkp} -> {Kl,Kp}       (z=2, A shared)
    hgemm<128,32,false,0,true,1>(hmt, nullptr, HID, 0, hWcat + 5 * WSQ, HID, WSQ,
                                 nullptr, hKm, HID, (long)M_DIM * HID, nullptr, nullptr, 0, 0,
                                 biascat + 5 * HID, HID, 1.f, M_DIM, HID, HID, 2);
    // 5) {Wvl,Wvp}^T-trick: V^T = W^T @ mt^T  (z=2, row bias)
    hgemm<128,32,false,0,true,2>(hWcat + 7 * WSQ, nullptr, HID, WSQ, hmt, HID, 0,
                                 nullptr, hVTm, M_DIM, (long)HID * M_DIM, nullptr, nullptr, 0, 0,
                                 biascat + 7 * HID, HID, 1.f, HID, M_DIM, HID, 2);

    // 6) attention scores (z=8 heads) -> fp16 score buffers
    hgemm<128,32,false,0,true,0>(hQlp, nullptr, HID, DH, hKm, HID, DH,
                                 nullptr, haw, HK, M_DIM, nullptr, nullptr, 0, 0,
                                 nullptr, 0, scale, L_DIM, M_DIM, DH, NH);
    hgemm<128,32,false,0,true,0>(hQlp + ES, nullptr, HID, DH, hKm + (long)M_DIM * HID, HID, DH,
                                 nullptr, haw + AS, HK, M_DIM, nullptr, nullptr, 0, 0,
                                 nullptr, 0, scale, P_DIM, M_DIM, DH, NH);

    // 7) masked softmax, in place (half2)
    softmax16_k<<<dim3(L_DIM, NH), 256>>>(haw, maskL);
    softmax16_k<<<dim3(P_DIM, NH), 256>>>(haw + AS, maskP);

    // 8) context (BN=64, NT vs V^T, relu) -> fp16 ctx
    hgemm<64,32,true,0,true,0>(haw, nullptr, HK, M_DIM, hVTm, M_DIM, (long)DH * M_DIM,
                               nullptr, hctx, HID, DH, nullptr, nullptr, 0, 0,
                               nullptr, 0, 1.f, L_DIM, DH, M_DIM, NH);
    hgemm<64,32,true,0,true,0>(haw + AS, nullptr, HK, M_DIM, hVTm + (long)HID * M_DIM, M_DIM, (long)DH * M_DIM,
                               nullptr, hctx + ES, HID, DH, nullptr, nullptr, 0, 0,
                               nullptr, 0, 1.f, P_DIM, DH, M_DIM, NH);

    // 9) transposes for the mutual chain (p first in the T buffers), 64x64 half2 tiles
    tconv_h2h64_k<<<dim3(HK / 64, P_DIM / 64), 256>>>(haw + AS, hawT, P_DIM, HK);
    tconv_h2h64_k<<<dim3(HK / 64, L_DIM / 64), 256>>>(haw, hawT + (size_t)HK * L_DIM, L_DIM, HK);
    tconv_h2h64_k<<<dim3(HID / 64, P_DIM / 64), 256>>>(hctx + ES, hctxT, P_DIM, HID);
    tconv_h2h64_k<<<dim3(HID / 64, L_DIM / 64), 256>>>(hctx, hctxT + (long)HID * L_DIM, L_DIM, HID);

    // 10) T-GEMMs batched (z=2): TpT = ctxp^T @ awp ; TlT = ctxl^T @ awl
    hgemm<128,32,false,0,true,0>(hctxT, nullptr, P_DIM, (long)HID * P_DIM, hawT, P_DIM, (long)HK * P_DIM,
                                 nullptr, hTT, HK, (long)HID * HK, nullptr, nullptr, 0, 0,
                                 nullptr, 0, 1.f, HID, HK, P_DIM, 2);
    // 11) fin batched (z=2): finl = ctxl + (1/H) awl @ TpT^T ; finp = ctxp + (1/H) awp @ TlT^T
    hgemm<128,32,false,2,true,0>(haw, nullptr, HK, AS, hTT, HK, (long)HID * HK,
                                 nullptr, hfin, HID, ES, nullptr, hctx, HID, ES,
                                 nullptr, 0, invH, L_DIM, HID, HK, 2);

    // 12) final linears: single K=1024 GEMM each via dual-A (concat semantics)
    hgemm<64,32,false,0,false,1,true>(hltpt, hfin, HID, 0, hWmlT, 2 * HID, 0,
                                      preL, nullptr, DHALF, 0, nullptr, nullptr, 0, 0,
                                      bml, 0, 1.f, L_DIM, DHALF, 2 * HID, 1);
    hgemm<64,32,false,0,false,1,true>(hfin + ES, hltpt + ES, HID, 0, hWmpT, 2 * HID, 0,
                                      preP, nullptr, DHALF, 0, nullptr, nullptr, 0, 0,
                                      bmp, 0, 1.f, P_DIM, DHALF, 2 * HID, 1);

    // 13) layernorms -> output
    float* out = (float*)d_out;
    ln_k<<<L_DIM, 256>>>(preL, g1, be1, out);
    ln_k<<<P_DIM, 256>>>(preP, g2, be2, out + (size_t)L_DIM * DHALF);
}

// round 12
// speedup vs baseline: 1.4499x; 1.4499x over previous
#include <cuda_runtime.h>
#include <cuda_fp16.h>
#include <math.h>
#include <stdint.h>

// Problem constants
#define L_DIM 4096
#define M_DIM 1024
#define P_DIM 4096
#define HID   512
#define NH    8
#define DH    64
#define HK    (NH * M_DIM)   // 8192 flattened (h, m)
#define DHALF 256
#define EPS_LN 1e-5f
#define WSQ   (HID * HID)

// ---------------- scratch (static device globals; no allocation) ----------------
__device__ float g_preL[L_DIM * DHALF];
__device__ float g_preP[P_DIM * DHALF];

// packed fp16 weights (transposed [N][K]) and packed biases
// slots: 0 Wl, 1 Wp, 2 Wm, 3 Wql, 4 Wqp, 5 Wkl, 6 Wkp, 7 Wvl, 8 Wvp
__device__ __half g_hWcat[9 * WSQ];
__device__ float  g_biascat[9 * HID];
__device__ __half g_hWmlT[DHALF * 2 * HID];   // [256][1024]
__device__ __half g_hWmpT[DHALF * 2 * HID];

// fp16 activations (L/P pairs contiguous for z-batching)
__device__ __half g_hEmb [2 * L_DIM * HID];            // Le, Pe
__device__ __half g_hMe  [M_DIM * HID];
__device__ __half g_hmt  [M_DIM * HID];
__device__ __half g_hltpt[2 * L_DIM * HID];            // lt, pt
__device__ __half g_hQlp [2 * L_DIM * HID];            // Ql, Qp
__device__ __half g_hKm  [2 * M_DIM * HID];            // Kl, Kp
__device__ __half g_hVTm [2 * HID * M_DIM];            // VlT, VpT  ([HID][M])
__device__ __half g_haw  [(size_t)2 * L_DIM * HK];     // awl, awp
__device__ __half g_hawT [(size_t)2 * HK * L_DIM];     // awpT, awlT  (note p first)
__device__ __half g_hctx [2 * L_DIM * HID];            // ctxl, ctxp
__device__ __half g_hctxT[2 * HID * L_DIM];            // ctxpT, ctxlT (p first)
__device__ __half g_hTT  [2 * HID * HK];               // TpT, TlT
__device__ __half g_hfin [2 * L_DIM * HID];            // finl, finp

// ================= fp16 tensor-core GEMM (mma.sync NT, 3-stage, strided/batched) =================
// C[M,N] = alpha * A[M,K](f16, ld=lda) @ B[N,K](f16, ld=ldb)^T  (+bias) (+Cadd) (relu)
// WTN: warp tile N (32). CADDM: 0 none, 1 f32 Cadd, 2 f16 Cadd.
// BIASM: 0 none, 1 per-col, 2 per-row.
// DUALA: A supplies K rows [0,Kd/2) and A2 supplies [Kd/2,Kd) (both ld=lda).
// Requires M%128==0, N%BN==0, K%32==0, K>=64 (all call sites exact).
#define HPAD 40

__device__ __forceinline__ uint32_t smem_u32(const void* p) {
    return (uint32_t)__cvta_generic_to_shared(p);
}

template<int BN, int WTN, bool RELU, int CADDM, bool OUTF16, int BIASM, bool DUALA>
__global__ void __launch_bounds__(256)
hgemm_k(const __half* __restrict__ A, const __half* __restrict__ A2, int lda, long sA,
        const __half* __restrict__ B, int ldb, long sB,
        float* __restrict__ C, __half* __restrict__ Ch, int ldc, long sC,
        const float* __restrict__ CaddF, const __half* __restrict__ CaddH,
        int ldadd, long sAdd,
        const float* __restrict__ bias, long sBias,
        float alpha, int Md, int Nd, int Kd)
{
    constexpr int BM = 128;
    constexpr int WN = BN / WTN;         // warps along N
    constexpr int WM = 8 / WN;           // warps along M
    constexpr int MI = BM / (WM * 16);   // m16 fragments per warp
    constexpr int NI = WTN / 8;          // n8 fragments per warp

    extern __shared__ __half hsm[];
    __half* sAb = hsm;                   // 3 stages x BM*HPAD
    __half* sBb = hsm + 3 * BM * HPAD;   // 3 stages x BN*HPAD

    const int tid  = threadIdx.x;
    const int wid  = tid >> 5, lane = tid & 31;
    const int wr   = wid / WN, wc = wid % WN;
    const int m0   = blockIdx.y * BM;
    const int n0   = blockIdx.x * BN;
    const long z   = blockIdx.z;

    A += z * sA;
    B += z * sB;

    float acc[MI][NI][4];
#pragma unroll
    for (int mi = 0; mi < MI; mi++)
#pragma unroll
        for (int ni = 0; ni < NI; ni++)
#pragma unroll
            for (int q = 0; q < 4; q++) acc[mi][ni][q] = 0.f;

    const int KT  = Kd / 32;
    const int KTH = Kd / 64;             // DUALA switch point

    auto load_stage = [&](int s, int kt) {
        __half* sa = sAb + s * BM * HPAD;
        __half* sb = sBb + s * BN * HPAD;
        const __half* Ause = A;
        int ktA = kt;
        if (DUALA && kt >= KTH) { Ause = A2; ktA = kt - KTH; }
#pragma unroll
        for (int i = 0; i < (BM * 4) / 256; i++) {
            int idx = tid + i * 256;
            int r = idx >> 2, u = idx & 3;
            const __half* g = Ause + (size_t)(m0 + r) * lda + ktA * 32 + u * 8;
            asm volatile("cp.async.ca.shared.global [%0], [%1], 16;\n"
                         :: "r"(smem_u32(&sa[r * HPAD + u * 8])), "l"(g));
        }
#pragma unroll
        for (int i = 0; i < (BN * 4) / 256; i++) {
            int idx = tid + i * 256;
            int r = idx >> 2, u = idx & 3;
            const __half* g = B + (size_t)(n0 + r) * ldb + kt * 32 + u * 8;
            asm volatile("cp.async.ca.shared.global [%0], [%1], 16;\n"
                         :: "r"(smem_u32(&sb[r * HPAD + u * 8])), "l"(g));
        }
        asm volatile("cp.async.commit_group;\n");
    };

    load_stage(0, 0);
    load_stage(1, 1);        // KT >= 2 at every call site

    for (int kt = 0; kt < KT; kt++) {
        const int s = kt % 3;
        if (kt + 1 < KT) { asm volatile("cp.async.wait_group 1;\n" ::: "memory"); }
        else             { asm volatile("cp.async.wait_group 0;\n" ::: "memory"); }
        __syncthreads();
        if (kt + 2 < KT) load_stage((kt + 2) % 3, kt + 2);

        const __half* sa = sAb + s * BM * HPAD;
        const __half* sb = sBb + s * BN * HPAD;

#pragma unroll
        for (int ks = 0; ks < 2; ks++) {
            uint32_t a[MI][4], b[NI][2];
#pragma unroll
            for (int mi = 0; mi < MI; mi++) {
                int row = wr * (MI * 16) + mi * 16 + (lane & 15);
                int col = ks * 16 + (lane >> 4) * 8;
                uint32_t addr = smem_u32(&sa[row * HPAD + col]);
                asm volatile("ldmatrix.sync.aligned.m8n8.x4.shared.b16 {%0,%1,%2,%3}, [%4];\n"
                             : "=r"(a[mi][0]), "=r"(a[mi][1]), "=r"(a[mi][2]), "=r"(a[mi][3])
                             : "r"(addr));
            }
#pragma unroll
            for (int j = 0; j < NI / 2; j++) {
                int n   = wc * WTN + j * 16 + (lane & 7) + ((lane >> 4) << 3);
                int col = ks * 16 + ((lane >> 3) & 1) * 8;
                uint32_t addr = smem_u32(&sb[n * HPAD + col]);
                uint32_t r0, r1, r2, r3;
                asm volatile("ldmatrix.sync.aligned.m8n8.x4.shared.b16 {%0,%1,%2,%3}, [%4];\n"
                             : "=r"(r0), "=r"(r1), "=r"(r2), "=r"(r3) : "r"(addr));
                b[2 * j][0] = r0; b[2 * j][1] = r1;
                b[2 * j + 1][0] = r2; b[2 * j + 1][1] = r3;
            }
#pragma unroll
            for (int mi = 0; mi < MI; mi++)
#pragma unroll
                for (int ni = 0; ni < NI; ni++)
                    asm volatile(
                        "mma.sync.aligned.m16n8k16.row.col.f32.f16.f16.f32 "
                        "{%0,%1,%2,%3}, {%4,%5,%6,%7}, {%8,%9}, {%0,%1,%2,%3};\n"
                        : "+f"(acc[mi][ni][0]), "+f"(acc[mi][ni][1]),
                          "+f"(acc[mi][ni][2]), "+f"(acc[mi][ni][3])
                        : "r"(a[mi][0]), "r"(a[mi][1]), "r"(a[mi][2]), "r"(a[mi][3]),
                          "r"(b[ni][0]), "r"(b[ni][1]));
        }
    }
    __syncthreads();

    // epilogue
    const float* bz = bias + z * sBias;
#pragma unroll
    for (int mi = 0; mi < MI; mi++) {
        int row = m0 + wr * (MI * 16) + mi * 16 + (lane >> 2);
#pragma unroll
        for (int ni = 0; ni < NI; ni++) {
            int col = n0 + wc * WTN + ni * 8 + (lane & 3) * 2;
            float2 lo = make_float2(acc[mi][ni][0] * alpha, acc[mi][ni][1] * alpha);
            float2 hi = make_float2(acc[mi][ni][2] * alpha, acc[mi][ni][3] * alpha);
            if (BIASM == 1) {
                float b0 = bz[col], b1 = bz[col + 1];
                lo.x += b0; lo.y += b1; hi.x += b0; hi.y += b1;
            }
            if (BIASM == 2) {
                float br = bz[row], br8 = bz[row + 8];
                lo.x += br; lo.y += br; hi.x += br8; hi.y += br8;
            }
            if (CADDM == 1) {
                const float* ca = CaddF + z * sAdd;
                float2 c0 = *(const float2*)&ca[(size_t)row * ldadd + col];
                float2 c1 = *(const float2*)&ca[(size_t)(row + 8) * ldadd + col];
                lo.x += c0.x; lo.y += c0.y;
                hi.x += c1.x; hi.y += c1.y;
            }
            if (CADDM == 2) {
                const __half* ca = CaddH + z * sAdd;
                float2 c0 = __half22float2(*(const __half2*)&ca[(size_t)row * ldadd + col]);
                float2 c1 = __half22float2(*(const __half2*)&ca[(size_t)(row + 8) * ldadd + col]);
                lo.x += c0.x; lo.y += c0.y;
                hi.x += c1.x; hi.y += c1.y;
            }
            if (RELU) {
                lo.x = fmaxf(lo.x, 0.f); lo.y = fmaxf(lo.y, 0.f);
                hi.x = fmaxf(hi.x, 0.f); hi.y = fmaxf(hi.y, 0.f);
            }
            if (OUTF16) {
                __half* co = Ch + z * sC;
                *(__half2*)&co[(size_t)row * ldc + col]       = __floats2half2_rn(lo.x, lo.y);
                *(__half2*)&co[(size_t)(row + 8) * ldc + col] = __floats2half2_rn(hi.x, hi.y);
            } else {
                float* co = C + z * sC;
                *(float2*)&co[(size_t)row * ldc + col]       = lo;
                *(float2*)&co[(size_t)(row + 8) * ldc + col] = hi;
            }
        }
    }
}

template<int BN, int WTN, bool RELU, int CADDM, bool OUTF16, int BIASM, bool DUALA = false>
static inline void hgemm(const __half* A, const __half* A2, int lda, long sA,
                         const __half* B, int ldb, long sB,
                         float* C, __half* Ch, int ldc, long sC,
                         const float* CaddF, const __half* CaddH, int ldadd, long sAdd,
                         const float* bias, long sBias, float alpha,
                         int Md, int Nd, int Kd, int batch)
{
    constexpr int SMEM = 3 * (128 + BN) * HPAD * 2;
    cudaFuncSetAttribute(hgemm_k<BN, WTN, RELU, CADDM, OUTF16, BIASM, DUALA>,
                         cudaFuncAttributeMaxDynamicSharedMemorySize, SMEM);
    dim3 grid(Nd / BN, Md / 128, batch);
    hgemm_k<BN, WTN, RELU, CADDM, OUTF16, BIASM, DUALA><<<grid, 256, SMEM>>>(
        A, A2, lda, sA, B, ldb, sB, C, Ch, ldc, sC, CaddF, CaddH, ldadd, sAdd,
        bias, sBias, alpha, Md, Nd, Kd);
}

// ---------------- conversions ----------------
__global__ void __launch_bounds__(256)
conv_k(const float4* __restrict__ in, __half2* __restrict__ out, int n4)
{
    int i = blockIdx.x * 256 + threadIdx.x;
    if (i < n4) {
        float4 v = in[i];
        out[2 * i]     = __floats2half2_rn(v.x, v.y);
        out[2 * i + 1] = __floats2half2_rn(v.z, v.w);
    }
}

// out[C][R] (f16) = transpose of in[R][C] (f32). R,C multiples of 32.
__global__ void __launch_bounds__(256)
tconv_f2h_k(const float* __restrict__ in, __half* __restrict__ out, int R, int C)
{
    __shared__ float t[32][33];
    int c0 = blockIdx.x * 32, r0 = blockIdx.y * 32;
    int x = threadIdx.x & 31, y = threadIdx.x >> 5;
#pragma unroll
    for (int j = 0; j < 32; j += 8)
        t[y + j][x] = in[(size_t)(r0 + y + j) * C + c0 + x];
    __syncthreads();
#pragma unroll
    for (int j = 0; j < 32; j += 8)
        out[(size_t)(c0 + y + j) * R + r0 + x] = __float2half(t[x][y + j]);
}

// out[C][R] (f16) = transpose of in[R][C] (f16). R,C multiples of 32.
__global__ void __launch_bounds__(256)
tconv_h2h_k(const __half* __restrict__ in, __half* __restrict__ out, int R, int C)
{
    __shared__ __half t[32][34];
    int c0 = blockIdx.x * 32, r0 = blockIdx.y * 32;
    int x = threadIdx.x & 31, y = threadIdx.x >> 5;
#pragma unroll
    for (int j = 0; j < 32; j += 8)
        t[y + j][x] = in[(size_t)(r0 + y + j) * C + c0 + x];
    __syncthreads();
#pragma unroll
    for (int j = 0; j < 32; j += 8)
        out[(size_t)(c0 + y + j) * R + r0 + x] = t[x][y + j];
}

// pack 9 bias vectors (512 each) into one contiguous buffer
__global__ void __launch_bounds__(512)
pack_bias_k(float* __restrict__ dst,
            const float* b0, const float* b1, const float* b2,
            const float* b3, const float* b4, const float* b5,
            const float* b6, const float* b7, const float* b8)
{
    int t = threadIdx.x;
    dst[0 * HID + t] = b0[t];
    dst[1 * HID + t] = b1[t];
    dst[2 * HID + t] = b2[t];
    dst[3 * HID + t] = b3[t];
    dst[4 * HID + t] = b4[t];
    dst[5 * HID + t] = b5[t];
    dst[6 * HID + t] = b6[t];
    dst[7 * HID + t] = b7[t];
    dst[8 * HID + t] = b8[t];
}

// ---------------- reductions ----------------
__device__ __forceinline__ float warpRedMax(float v) {
#pragma unroll
    for (int o = 16; o > 0; o >>= 1) v = fmaxf(v, __shfl_xor_sync(0xffffffffu, v, o));
    return v;
}
__device__ __forceinline__ float warpRedSum(float v) {
#pragma unroll
    for (int o = 16; o > 0; o >>= 1) v += __shfl_xor_sync(0xffffffffu, v, o);
    return v;
}
__device__ __forceinline__ float blockMax256(float v, float* red) {
    int lane = threadIdx.x & 31, w = threadIdx.x >> 5;
    v = warpRedMax(v);
    if (lane == 0) red[w] = v;
    __syncthreads();
    float r = red[0];
#pragma unroll
    for (int i = 1; i < 8; i++) r = fmaxf(r, red[i]);
    __syncthreads();
    return r;
}
__device__ __forceinline__ float blockSum256(float v, float* red) {
    int lane = threadIdx.x & 31, w = threadIdx.x >> 5;
    v = warpRedSum(v);
    if (lane == 0) red[w] = v;
    __syncthreads();
    float r = 0.f;
#pragma unroll
    for (int i = 0; i < 8; i++) r += red[i];
    __syncthreads();
    return r;
}

// ---------------- masked softmax, in place on fp16 scores (half2-vectorized) ----------------
__global__ void __launch_bounds__(256)
softmax16_k(__half* __restrict__ S, const int* __restrict__ mask)
{
    __shared__ float red[8];
    const int l = blockIdx.x, h = blockIdx.y;
    __half2* row2 = (__half2*)(S + (size_t)l * HK + (size_t)h * M_DIM);
    const int2* m2 = (const int2*)(mask + (size_t)l * M_DIM);
    const int t = threadIdx.x;

    float2 v[2];
    float mx = -3.4e38f;
#pragma unroll
    for (int i = 0; i < 2; i++) {
        int m = t + i * 256;
        float2 f = __half22float2(row2[m]);
        int2  mm = m2[m];
        f.x = (mm.x != 0) ? f.x : -1e9f;
        f.y = (mm.y != 0) ? f.y : -1e9f;
        v[i] = f;
        mx = fmaxf(mx, fmaxf(f.x, f.y));
    }
    mx = blockMax256(mx, red);
    float sum = 0.f;
#pragma unroll
    for (int i = 0; i < 2; i++) {
        v[i].x = __expf(v[i].x - mx);
        v[i].y = __expf(v[i].y - mx);
        sum += v[i].x + v[i].y;
    }
    sum = blockSum256(sum, red);
    float inv = __frcp_rn(sum);
#pragma unroll
    for (int i = 0; i < 2; i++)
        row2[t + i * 256] = __floats2half2_rn(v[i].x * inv, v[i].y * inv);
}

// ---------------- layernorm ----------------
__global__ void __launch_bounds__(256)
ln_k(const float* __restrict__ x, const float* __restrict__ g, const float* __restrict__ be,
     float* __restrict__ out)
{
    __shared__ float red[8];
    const int r = blockIdx.x, t = threadIdx.x;
    float v = x[r * 256 + t];
    float mean = blockSum256(v, red) * (1.f / 256.f);
    float d = v - mean;
    float var = blockSum256(d * d, red) * (1.f / 256.f);
    out[r * 256 + t] = d * rsqrtf(var + EPS_LN) * g[t] + be[t];
}

// ---------------- launch ----------------
static inline void* symraw(const void* s) {
    void* p = nullptr;
    cudaGetSymbolAddress(&p, s);
    return p;
}

extern "C" void kernel_launch(void* const* d_in, const int* in_sizes, int n_in,
                              void* d_out, int out_size)
{
    (void)in_sizes; (void)n_in; (void)out_size;
    const float* Le    = (const float*)d_in[0];
    const float* Me    = (const float*)d_in[1];
    const float* Pe    = (const float*)d_in[2];
    const int*   maskL = (const int*)  d_in[3];
    const int*   maskP = (const int*)  d_in[4];
    const float *Wl  = (const float*)d_in[5],  *bl  = (const float*)d_in[6];
    const float *Wm  = (const float*)d_in[7],  *bm  = (const float*)d_in[8];
    const float *Wp  = (const float*)d_in[9],  *bp  = (const float*)d_in[10];
    const float *Wql = (const float*)d_in[11], *bql = (const float*)d_in[12];
    const float *Wkl = (const float*)d_in[13], *bkl = (const float*)d_in[14];
    const float *Wvl = (const float*)d_in[15], *bvl = (const float*)d_in[16];
    const float *Wqp = (const float*)d_in[17], *bqp = (const float*)d_in[18];
    const float *Wkp = (const float*)d_in[19], *bkp = (const float*)d_in[20];
    const float *Wvp = (const float*)d_in[21], *bvp = (const float*)d_in[22];
    const float *Wml = (const float*)d_in[23], *bml = (const float*)d_in[24];
    const float *Wmp = (const float*)d_in[25], *bmp = (const float*)d_in[26];
    const float *g1  = (const float*)d_in[27], *be1 = (const float*)d_in[28];
    const float *g2  = (const float*)d_in[29], *be2 = (const float*)d_in[30];

    float* preL = (float*)symraw(g_preL);
    float* preP = (float*)symraw(g_preP);

    __half* hWcat  = (__half*)symraw(g_hWcat);
    float*  biascat= (float*) symraw(g_biascat);
    __half* hWmlT  = (__half*)symraw(g_hWmlT);
    __half* hWmpT  = (__half*)symraw(g_hWmpT);

    __half* hEmb  = (__half*)symraw(g_hEmb);
    __half* hMe   = (__half*)symraw(g_hMe);
    __half* hmt   = (__half*)symraw(g_hmt);
    __half* hltpt = (__half*)symraw(g_hltpt);
    __half* hQlp  = (__half*)symraw(g_hQlp);
    __half* hKm   = (__half*)symraw(g_hKm);
    __half* hVTm  = (__half*)symraw(g_hVTm);
    __half* haw   = (__half*)symraw(g_haw);
    __half* hawT  = (__half*)symraw(g_hawT);
    __half* hctx  = (__half*)symraw(g_hctx);
    __half* hctxT = (__half*)symraw(g_hctxT);
    __half* hTT   = (__half*)symraw(g_hTT);
    __half* hfin  = (__half*)symraw(g_hfin);

    const float scale = 0.125f;   // 1/sqrt(DH)
    const float invH  = 0.125f;   // 1/H

    const long ES = (long)L_DIM * HID;     // embedding-sized stride
    const long AS = (long)L_DIM * HK;      // attention-map stride

    // 0) inputs + weights -> fp16 (weights transposed to [N][K], packed)
    conv_k<<<(L_DIM * HID / 4 + 255) / 256, 256>>>((const float4*)Le, (__half2*)hEmb, L_DIM * HID / 4);
    conv_k<<<(P_DIM * HID / 4 + 255) / 256, 256>>>((const float4*)Pe, (__half2*)(hEmb + ES), P_DIM * HID / 4);
    conv_k<<<(M_DIM * HID / 4 + 255) / 256, 256>>>((const float4*)Me, (__half2*)hMe, M_DIM * HID / 4);
    {
        dim3 gw(HID / 32, HID / 32);
        tconv_f2h_k<<<gw, 256>>>(Wl,  hWcat + 0 * WSQ, HID, HID);
        tconv_f2h_k<<<gw, 256>>>(Wp,  hWcat + 1 * WSQ, HID, HID);
        tconv_f2h_k<<<gw, 256>>>(Wm,  hWcat + 2 * WSQ, HID, HID);
        tconv_f2h_k<<<gw, 256>>>(Wql, hWcat + 3 * WSQ, HID, HID);
        tconv_f2h_k<<<gw, 256>>>(Wqp, hWcat + 4 * WSQ, HID, HID);
        tconv_f2h_k<<<gw, 256>>>(Wkl, hWcat + 5 * WSQ, HID, HID);
        tconv_f2h_k<<<gw, 256>>>(Wkp, hWcat + 6 * WSQ, HID, HID);
        tconv_f2h_k<<<gw, 256>>>(Wvl, hWcat + 7 * WSQ, HID, HID);
        tconv_f2h_k<<<gw, 256>>>(Wvp, hWcat + 8 * WSQ, HID, HID);
        dim3 gw2(DHALF / 32, 2 * HID / 32);
        tconv_f2h_k<<<gw2, 256>>>(Wml, hWmlT, 2 * HID, DHALF);
        tconv_f2h_k<<<gw2, 256>>>(Wmp, hWmpT, 2 * HID, DHALF);
    }
    pack_bias_k<<<1, 512>>>(biascat, bl, bp, bm, bql, bqp, bkl, bkp, bvl, bvp);

    // 1) {Le,Pe} @ {Wl,Wp} -> {lt,pt}   (z=2)
    hgemm<128,32,false,0,true,1>(hEmb, nullptr, HID, ES, hWcat, HID, WSQ,
                                 nullptr, hltpt, HID, ES, nullptr, nullptr, 0, 0,
                                 biascat, HID, 1.f, L_DIM, HID, HID, 2);
    // 2) Me @ Wm -> mt
    hgemm<128,32,false,0,true,1>(hMe, nullptr, HID, 0, hWcat + 2 * WSQ, HID, 0,
                                 nullptr, hmt, HID, 0, nullptr, nullptr, 0, 0,
                                 biascat + 2 * HID, 0, 1.f, M_DIM, HID, HID, 1);
    // 3) {lt,pt} @ {Wql,Wqp} -> {Ql,Qp}  (z=2)
    hgemm<128,32,false,0,true,1>(hltpt, nullptr, HID, ES, hWcat + 3 * WSQ, HID, WSQ,
                                 nullptr, hQlp, HID, ES, nullptr, nullptr, 0, 0,
                                 biascat + 3 * HID, HID, 1.f, L_DIM, HID, HID, 2);
    // 4) mt @ {Wkl,Wkp} -> {Kl,Kp}       (z=2, A shared)
    hgemm<128,32,false,0,true,1>(hmt, nullptr, HID, 0, hWcat + 5 * WSQ, HID, WSQ,
                                 nullptr, hKm, HID, (long)M_DIM * HID, nullptr, nullptr, 0, 0,
                                 biascat + 5 * HID, HID, 1.f, M_DIM, HID, HID, 2);
    // 5) {Wvl,Wvp}^T-trick: V^T = W^T @ mt^T  (z=2, row bias)
    hgemm<128,32,false,0,true,2>(hWcat + 7 * WSQ, nullptr, HID, WSQ, hmt, HID, 0,
                                 nullptr, hVTm, M_DIM, (long)HID * M_DIM, nullptr, nullptr, 0, 0,
                                 biascat + 7 * HID, HID, 1.f, HID, M_DIM, HID, 2);

    // 6) attention scores (z=8 heads) -> fp16 score buffers
    hgemm<128,32,false,0,true,0>(hQlp, nullptr, HID, DH, hKm, HID, DH,
                                 nullptr, haw, HK, M_DIM, nullptr, nullptr, 0, 0,
                                 nullptr, 0, scale, L_DIM, M_DIM, DH, NH);
    hgemm<128,32,false,0,true,0>(hQlp + ES, nullptr, HID, DH, hKm + (long)M_DIM * HID, HID, DH,
                                 nullptr, haw + AS, HK, M_DIM, nullptr, nullptr, 0, 0,
                                 nullptr, 0, scale, P_DIM, M_DIM, DH, NH);

    // 7) masked softmax, in place (half2)
    softmax16_k<<<dim3(L_DIM, NH), 256>>>(haw, maskL);
    softmax16_k<<<dim3(P_DIM, NH), 256>>>(haw + AS, maskP);

    // 8) context (BN=64, NT vs V^T, relu) -> fp16 ctx
    hgemm<64,32,true,0,true,0>(haw, nullptr, HK, M_DIM, hVTm, M_DIM, (long)DH * M_DIM,
                               nullptr, hctx, HID, DH, nullptr, nullptr, 0, 0,
                               nullptr, 0, 1.f, L_DIM, DH, M_DIM, NH);
    hgemm<64,32,true,0,true,0>(haw + AS, nullptr, HK, M_DIM, hVTm + (long)HID * M_DIM, M_DIM, (long)DH * M_DIM,
                               nullptr, hctx + ES, HID, DH, nullptr, nullptr, 0, 0,
                               nullptr, 0, 1.f, P_DIM, DH, M_DIM, NH);

    // 9) transposes for the mutual chain (p first in the T buffers)
    tconv_h2h_k<<<dim3(HK / 32, P_DIM / 32), 256>>>(haw + AS, hawT, P_DIM, HK);
    tconv_h2h_k<<<dim3(HK / 32, L_DIM / 32), 256>>>(haw, hawT + (size_t)HK * L_DIM, L_DIM, HK);
    tconv_h2h_k<<<dim3(HID / 32, P_DIM / 32), 256>>>(hctx + ES, hctxT, P_DIM, HID);
    tconv_h2h_k<<<dim3(HID / 32, L_DIM / 32), 256>>>(hctx, hctxT + (long)HID * L_DIM, L_DIM, HID);

    // 10) T-GEMMs batched (z=2): TpT = ctxp^T @ awp ; TlT = ctxl^T @ awl
    hgemm<128,32,false,0,true,0>(hctxT, nullptr, P_DIM, (long)HID * P_DIM, hawT, P_DIM, (long)HK * P_DIM,
                                 nullptr, hTT, HK, (long)HID * HK, nullptr, nullptr, 0, 0,
                                 nullptr, 0, 1.f, HID, HK, P_DIM, 2);
    // 11) fin batched (z=2): finl = ctxl + (1/H) awl @ TpT^T ; finp = ctxp + (1/H) awp @ TlT^T
    hgemm<128,32,false,2,true,0>(haw, nullptr, HK, AS, hTT, HK, (long)HID * HK,
                                 nullptr, hfin, HID, ES, nullptr, hctx, HID, ES,
                                 nullptr, 0, invH, L_DIM, HID, HK, 2);

    // 12) final linears: single K=1024 GEMM each via dual-A (concat semantics)
    hgemm<64,32,false,0,false,1,true>(hltpt, hfin, HID, 0, hWmlT, 2 * HID, 0,
                                      preL, nullptr, DHALF, 0, nullptr, nullptr, 0, 0,
                                      bml, 0, 1.f, L_DIM, DHALF, 2 * HID, 1);
    hgemm<64,32,false,0,false,1,true>(hfin + ES, hltpt + ES, HID, 0, hWmpT, 2 * HID, 0,
                                      preP, nullptr, DHALF, 0, nullptr, nullptr, 0, 0,
                                      bmp, 0, 1.f, P_DIM, DHALF, 2 * HID, 1);

    // 13) layernorms -> output
    float* out = (float*)d_out;
    ln_k<<<L_DIM, 256>>>(preL, g1, be1, out);
    ln_k<<<P_DIM, 256>>>(preP, g2, be2, out + (size_t)L_DIM * DHALF);
}

// round 13
// speedup vs baseline: 1.5543x; 1.0720x over previous
#include <cuda_runtime.h>
#include <cuda_fp16.h>
#include <math.h>
#include <stdint.h>

// Problem constants
#define L_DIM 4096
#define M_DIM 1024
#define P_DIM 4096
#define HID   512
#define NH    8
#define DH    64
#define HK    (NH * M_DIM)   // 8192 flattened (h, m)
#define DHALF 256
#define EPS_LN 1e-5f
#define WSQ   (HID * HID)

// ---------------- scratch (static device globals; no allocation) ----------------
__device__ float g_preL[L_DIM * DHALF];
__device__ float g_preP[P_DIM * DHALF];

// packed fp16 weights (transposed [N][K]) and packed biases
// slots: 0 Wl, 1 Wp, 2 Wm, 3 Wql, 4 Wqp, 5 Wkl, 6 Wkp, 7 Wvl, 8 Wvp
__device__ __half g_hWcat[9 * WSQ];
__device__ float  g_biascat[9 * HID];
__device__ __half g_hWmlT[DHALF * 2 * HID];   // [256][1024]
__device__ __half g_hWmpT[DHALF * 2 * HID];

// fp16 activations (L/P pairs contiguous for z-batching)
__device__ __half g_hEmb [2 * L_DIM * HID];            // Le, Pe
__device__ __half g_hMe  [M_DIM * HID];
__device__ __half g_hmt  [M_DIM * HID];
__device__ __half g_hltpt[2 * L_DIM * HID];            // lt, pt
__device__ __half g_hQlp [2 * L_DIM * HID];            // Ql, Qp
__device__ __half g_hKm  [2 * M_DIM * HID];            // Kl, Kp
__device__ __half g_hVTm [2 * HID * M_DIM];            // VlT, VpT  ([HID][M])
__device__ __half g_haw  [(size_t)2 * L_DIM * HK];     // awl, awp
__device__ __half g_hawT [(size_t)2 * HK * L_DIM];     // awpT, awlT  (note p first)
__device__ __half g_hctx [2 * L_DIM * HID];            // ctxl, ctxp
__device__ __half g_hctxT[2 * HID * L_DIM];            // ctxpT, ctxlT (p first)
__device__ __half g_hTT  [2 * HID * HK];               // TpT, TlT
__device__ __half g_hfin [2 * L_DIM * HID];            // finl, finp

// ================= fp16 tensor-core GEMM (mma.sync NT, 3-stage, strided/batched) =================
// C[M,N] = alpha * A[M,K](f16, ld=lda) @ B[N,K](f16, ld=ldb)^T  (+bias) (+Cadd) (relu)
// WTN: warp tile N (32). CADDM: 0 none, 1 f32 Cadd, 2 f16 Cadd.
// BIASM: 0 none, 1 per-col, 2 per-row.
// DUALA: A supplies K rows [0,Kd/2) and A2 supplies [Kd/2,Kd) (both ld=lda).
// Requires M%128==0, N%BN==0, K%32==0, K>=64 (all call sites exact).
#define HPAD 40

__device__ __forceinline__ uint32_t smem_u32(const void* p) {
    return (uint32_t)__cvta_generic_to_shared(p);
}

template<int BN, int WTN, bool RELU, int CADDM, bool OUTF16, int BIASM, bool DUALA>
__global__ void __launch_bounds__(256)
hgemm_k(const __half* __restrict__ A, const __half* __restrict__ A2, int lda, long sA,
        const __half* __restrict__ B, int ldb, long sB,
        float* __restrict__ C, __half* __restrict__ Ch, int ldc, long sC,
        const float* __restrict__ CaddF, const __half* __restrict__ CaddH,
        int ldadd, long sAdd,
        const float* __restrict__ bias, long sBias,
        float alpha, int Md, int Nd, int Kd)
{
    constexpr int BM = 128;
    constexpr int WN = BN / WTN;         // warps along N
    constexpr int WM = 8 / WN;           // warps along M
    constexpr int MI = BM / (WM * 16);   // m16 fragments per warp
    constexpr int NI = WTN / 8;          // n8 fragments per warp

    extern __shared__ __half hsm[];
    __half* sAb = hsm;                   // 3 stages x BM*HPAD
    __half* sBb = hsm + 3 * BM * HPAD;   // 3 stages x BN*HPAD

    const int tid  = threadIdx.x;
    const int wid  = tid >> 5, lane = tid & 31;
    const int wr   = wid / WN, wc = wid % WN;
    const int m0   = blockIdx.y * BM;
    const int n0   = blockIdx.x * BN;
    const long z   = blockIdx.z;

    A += z * sA;
    B += z * sB;

    float acc[MI][NI][4];
#pragma unroll
    for (int mi = 0; mi < MI; mi++)
#pragma unroll
        for (int ni = 0; ni < NI; ni++)
#pragma unroll
            for (int q = 0; q < 4; q++) acc[mi][ni][q] = 0.f;

    const int KT  = Kd / 32;
    const int KTH = Kd / 64;             // DUALA switch point

    auto load_stage = [&](int s, int kt) {
        __half* sa = sAb + s * BM * HPAD;
        __half* sb = sBb + s * BN * HPAD;
        const __half* Ause = A;
        int ktA = kt;
        if (DUALA && kt >= KTH) { Ause = A2; ktA = kt - KTH; }
#pragma unroll
        for (int i = 0; i < (BM * 4) / 256; i++) {
            int idx = tid + i * 256;
            int r = idx >> 2, u = idx & 3;
            const __half* g = Ause + (size_t)(m0 + r) * lda + ktA * 32 + u * 8;
            asm volatile("cp.async.ca.shared.global [%0], [%1], 16;\n"
                         :: "r"(smem_u32(&sa[r * HPAD + u * 8])), "l"(g));
        }
#pragma unroll
        for (int i = 0; i < (BN * 4) / 256; i++) {
            int idx = tid + i * 256;
            int r = idx >> 2, u = idx & 3;
            const __half* g = B + (size_t)(n0 + r) * ldb + kt * 32 + u * 8;
            asm volatile("cp.async.ca.shared.global [%0], [%1], 16;\n"
                         :: "r"(smem_u32(&sb[r * HPAD + u * 8])), "l"(g));
        }
        asm volatile("cp.async.commit_group;\n");
    };

    load_stage(0, 0);
    load_stage(1, 1);        // KT >= 2 at every call site

    for (int kt = 0; kt < KT; kt++) {
        const int s = kt % 3;
        if (kt + 1 < KT) { asm volatile("cp.async.wait_group 1;\n" ::: "memory"); }
        else             { asm volatile("cp.async.wait_group 0;\n" ::: "memory"); }
        __syncthreads();
        if (kt + 2 < KT) load_stage((kt + 2) % 3, kt + 2);

        const __half* sa = sAb + s * BM * HPAD;
        const __half* sb = sBb + s * BN * HPAD;

#pragma unroll
        for (int ks = 0; ks < 2; ks++) {
            uint32_t a[MI][4], b[NI][2];
#pragma unroll
            for (int mi = 0; mi < MI; mi++) {
                int row = wr * (MI * 16) + mi * 16 + (lane & 15);
                int col = ks * 16 + (lane >> 4) * 8;
                uint32_t addr = smem_u32(&sa[row * HPAD + col]);
                asm volatile("ldmatrix.sync.aligned.m8n8.x4.shared.b16 {%0,%1,%2,%3}, [%4];\n"
                             : "=r"(a[mi][0]), "=r"(a[mi][1]), "=r"(a[mi][2]), "=r"(a[mi][3])
                             : "r"(addr));
            }
#pragma unroll
            for (int j = 0; j < NI / 2; j++) {
                int n   = wc * WTN + j * 16 + (lane & 7) + ((lane >> 4) << 3);
                int col = ks * 16 + ((lane >> 3) & 1) * 8;
                uint32_t addr = smem_u32(&sb[n * HPAD + col]);
                uint32_t r0, r1, r2, r3;
                asm volatile("ldmatrix.sync.aligned.m8n8.x4.shared.b16 {%0,%1,%2,%3}, [%4];\n"
                             : "=r"(r0), "=r"(r1), "=r"(r2), "=r"(r3) : "r"(addr));
                b[2 * j][0] = r0; b[2 * j][1] = r1;
                b[2 * j + 1][0] = r2; b[2 * j + 1][1] = r3;
            }
#pragma unroll
            for (int mi = 0; mi < MI; mi++)
#pragma unroll
                for (int ni = 0; ni < NI; ni++)
                    asm volatile(
                        "mma.sync.aligned.m16n8k16.row.col.f32.f16.f16.f32 "
                        "{%0,%1,%2,%3}, {%4,%5,%6,%7}, {%8,%9}, {%0,%1,%2,%3};\n"
                        : "+f"(acc[mi][ni][0]), "+f"(acc[mi][ni][1]),
                          "+f"(acc[mi][ni][2]), "+f"(acc[mi][ni][3])
                        : "r"(a[mi][0]), "r"(a[mi][1]), "r"(a[mi][2]), "r"(a[mi][3]),
                          "r"(b[ni][0]), "r"(b[ni][1]));
        }
    }
    __syncthreads();

    // epilogue
    const float* bz = bias + z * sBias;
#pragma unroll
    for (int mi = 0; mi < MI; mi++) {
        int row = m0 + wr * (MI * 16) + mi * 16 + (lane >> 2);
#pragma unroll
        for (int ni = 0; ni < NI; ni++) {
            int col = n0 + wc * WTN + ni * 8 + (lane & 3) * 2;
            float2 lo = make_float2(acc[mi][ni][0] * alpha, acc[mi][ni][1] * alpha);
            float2 hi = make_float2(acc[mi][ni][2] * alpha, acc[mi][ni][3] * alpha);
            if (BIASM == 1) {
                float b0 = bz[col], b1 = bz[col + 1];
                lo.x += b0; lo.y += b1; hi.x += b0; hi.y += b1;
            }
            if (BIASM == 2) {
                float br = bz[row], br8 = bz[row + 8];
                lo.x += br; lo.y += br; hi.x += br8; hi.y += br8;
            }
            if (CADDM == 1) {
                const float* ca = CaddF + z * sAdd;
                float2 c0 = *(const float2*)&ca[(size_t)row * ldadd + col];
                float2 c1 = *(const float2*)&ca[(size_t)(row + 8) * ldadd + col];
                lo.x += c0.x; lo.y += c0.y;
                hi.x += c1.x; hi.y += c1.y;
            }
            if (CADDM == 2) {
                const __half* ca = CaddH + z * sAdd;
                float2 c0 = __half22float2(*(const __half2*)&ca[(size_t)row * ldadd + col]);
                float2 c1 = __half22float2(*(const __half2*)&ca[(size_t)(row + 8) * ldadd + col]);
                lo.x += c0.x; lo.y += c0.y;
                hi.x += c1.x; hi.y += c1.y;
            }
            if (RELU) {
                lo.x = fmaxf(lo.x, 0.f); lo.y = fmaxf(lo.y, 0.f);
                hi.x = fmaxf(hi.x, 0.f); hi.y = fmaxf(hi.y, 0.f);
            }
            if (OUTF16) {
                __half* co = Ch + z * sC;
                *(__half2*)&co[(size_t)row * ldc + col]       = __floats2half2_rn(lo.x, lo.y);
                *(__half2*)&co[(size_t)(row + 8) * ldc + col] = __floats2half2_rn(hi.x, hi.y);
            } else {
                float* co = C + z * sC;
                *(float2*)&co[(size_t)row * ldc + col]       = lo;
                *(float2*)&co[(size_t)(row + 8) * ldc + col] = hi;
            }
        }
    }
}

template<int BN, int WTN, bool RELU, int CADDM, bool OUTF16, int BIASM, bool DUALA = false>
static inline void hgemm(const __half* A, const __half* A2, int lda, long sA,
                         const __half* B, int ldb, long sB,
                         float* C, __half* Ch, int ldc, long sC,
                         const float* CaddF, const __half* CaddH, int ldadd, long sAdd,
                         const float* bias, long sBias, float alpha,
                         int Md, int Nd, int Kd, int batch)
{
    constexpr int SMEM = 3 * (128 + BN) * HPAD * 2;
    cudaFuncSetAttribute(hgemm_k<BN, WTN, RELU, CADDM, OUTF16, BIASM, DUALA>,
                         cudaFuncAttributeMaxDynamicSharedMemorySize, SMEM);
    dim3 grid(Nd / BN, Md / 128, batch);
    hgemm_k<BN, WTN, RELU, CADDM, OUTF16, BIASM, DUALA><<<grid, 256, SMEM>>>(
        A, A2, lda, sA, B, ldb, sB, C, Ch, ldc, sC, CaddF, CaddH, ldadd, sAdd,
        bias, sBias, alpha, Md, Nd, Kd);
}

// ---------------- conversions ----------------
__global__ void __launch_bounds__(256)
conv_k(const float4* __restrict__ in, __half2* __restrict__ out, int n4)
{
    int i = blockIdx.x * 256 + threadIdx.x;
    if (i < n4) {
        float4 v = in[i];
        out[2 * i]     = __floats2half2_rn(v.x, v.y);
        out[2 * i + 1] = __floats2half2_rn(v.z, v.w);
    }
}

// out[C][R] (f16) = transpose of in[R][C] (f32). R,C multiples of 32.
__global__ void __launch_bounds__(256)
tconv_f2h_k(const float* __restrict__ in, __half* __restrict__ out, int R, int C)
{
    __shared__ float t[32][33];
    int c0 = blockIdx.x * 32, r0 = blockIdx.y * 32;
    int x = threadIdx.x & 31, y = threadIdx.x >> 5;
#pragma unroll
    for (int j = 0; j < 32; j += 8)
        t[y + j][x] = in[(size_t)(r0 + y + j) * C + c0 + x];
    __syncthreads();
#pragma unroll
    for (int j = 0; j < 32; j += 8)
        out[(size_t)(c0 + y + j) * R + r0 + x] = __float2half(t[x][y + j]);
}

// out[C][R] (f16) = transpose of in[R][C] (f16). R,C multiples of 32.
__global__ void __launch_bounds__(256)
tconv_h2h_k(const __half* __restrict__ in, __half* __restrict__ out, int R, int C)
{
    __shared__ __half t[32][34];
    int c0 = blockIdx.x * 32, r0 = blockIdx.y * 32;
    int x = threadIdx.x & 31, y = threadIdx.x >> 5;
#pragma unroll
    for (int j = 0; j < 32; j += 8)
        t[y + j][x] = in[(size_t)(r0 + y + j) * C + c0 + x];
    __syncthreads();
#pragma unroll
    for (int j = 0; j < 32; j += 8)
        out[(size_t)(c0 + y + j) * R + r0 + x] = t[x][y + j];
}

// pack 9 bias vectors (512 each) into one contiguous buffer
__global__ void __launch_bounds__(512)
pack_bias_k(float* __restrict__ dst,
            const float* b0, const float* b1, const float* b2,
            const float* b3, const float* b4, const float* b5,
            const float* b6, const float* b7, const float* b8)
{
    int t = threadIdx.x;
    dst[0 * HID + t] = b0[t];
    dst[1 * HID + t] = b1[t];
    dst[2 * HID + t] = b2[t];
    dst[3 * HID + t] = b3[t];
    dst[4 * HID + t] = b4[t];
    dst[5 * HID + t] = b5[t];
    dst[6 * HID + t] = b6[t];
    dst[7 * HID + t] = b7[t];
    dst[8 * HID + t] = b8[t];
}

// ---------------- reductions ----------------
__device__ __forceinline__ float warpRedMax(float v) {
#pragma unroll
    for (int o = 16; o > 0; o >>= 1) v = fmaxf(v, __shfl_xor_sync(0xffffffffu, v, o));
    return v;
}
__device__ __forceinline__ float warpRedSum(float v) {
#pragma unroll
    for (int o = 16; o > 0; o >>= 1) v += __shfl_xor_sync(0xffffffffu, v, o);
    return v;
}
__device__ __forceinline__ float blockSum256(float v, float* red) {
    int lane = threadIdx.x & 31, w = threadIdx.x >> 5;
    v = warpRedSum(v);
    if (lane == 0) red[w] = v;
    __syncthreads();
    float r = 0.f;
#pragma unroll
    for (int i = 0; i < 8; i++) r += red[i];
    __syncthreads();
    return r;
}

// ---------------- fused masked softmax + transpose (fp16) ----------------
// Block: 32 rows (l) x 1024 (m) of head h. Normalizes in place into S and
// writes the transpose into ST[(h*M + m) * R + l].
#define SMT_PITCH 1026   // halves; 1026*2B = 2052B -> 513 banks -> conflict-free columns
#define SMT_BYTES (32 * SMT_PITCH * 2)

__global__ void __launch_bounds__(256)
softmaxT_k(__half* __restrict__ S, __half* __restrict__ ST,
           const int* __restrict__ mask, int R)
{
    extern __shared__ __half sm[];
    const int h  = blockIdx.y;
    const int l0 = blockIdx.x * 32;
    const int wid = threadIdx.x >> 5, lane = threadIdx.x & 31;

    // each warp handles 4 rows: wid, wid+8, wid+16, wid+24
#pragma unroll 1
    for (int rr = 0; rr < 4; rr++) {
        const int row = rr * 8 + wid;
        const int l = l0 + row;
        const __half2* src = (const __half2*)(S + (size_t)l * HK + (size_t)h * M_DIM);
        const int2*    m2  = (const int2*)(mask + (size_t)l * M_DIM);

        float2 v[16];
        float mx = -3.4e38f;
#pragma unroll
        for (int i = 0; i < 16; i++) {
            float2 f = __half22float2(src[lane + i * 32]);
            int2  mm = m2[lane + i * 32];
            f.x = (mm.x != 0) ? f.x : -1e9f;
            f.y = (mm.y != 0) ? f.y : -1e9f;
            v[i] = f;
            mx = fmaxf(mx, fmaxf(f.x, f.y));
        }
        mx = warpRedMax(mx);
        float sum = 0.f;
#pragma unroll
        for (int i = 0; i < 16; i++) {
            v[i].x = __expf(v[i].x - mx);
            v[i].y = __expf(v[i].y - mx);
            sum += v[i].x + v[i].y;
        }
        sum = warpRedSum(sum);
        float inv = __frcp_rn(sum);

        __half2* srow = (__half2*)(sm + row * SMT_PITCH);
#pragma unroll
        for (int i = 0; i < 16; i++)
            srow[lane + i * 32] = __floats2half2_rn(v[i].x * inv, v[i].y * inv);
    }
    __syncthreads();

    // write normalized S back (coalesced half2)
    for (int idx = threadIdx.x; idx < 32 * 512; idx += 256) {
        int row = idx >> 9, c2 = idx & 511;
        __half2 hv = ((const __half2*)(sm + row * SMT_PITCH))[c2];
        ((__half2*)(S + (size_t)(l0 + row) * HK + (size_t)h * M_DIM))[c2] = hv;
    }
    // write transpose: ST[(h*M + m) * R + l0 + 0..31], half2 along l
    for (int idx = threadIdx.x; idx < 1024 * 16; idx += 256) {
        int m = idx >> 4, lp = idx & 15;
        __half a = sm[(2 * lp)     * SMT_PITCH + m];
        __half b = sm[(2 * lp + 1) * SMT_PITCH + m];
        ((__half2*)(ST + (size_t)(h * M_DIM + m) * R + l0))[lp] = __halves2half2(a, b);
    }
}

// ---------------- layernorm ----------------
__global__ void __launch_bounds__(256)
ln_k(const float* __restrict__ x, const float* __restrict__ g, const float* __restrict__ be,
     float* __restrict__ out)
{
    __shared__ float red[8];
    const int r = blockIdx.x, t = threadIdx.x;
    float v = x[r * 256 + t];
    float mean = blockSum256(v, red) * (1.f / 256.f);
    float d = v - mean;
    float var = blockSum256(d * d, red) * (1.f / 256.f);
    out[r * 256 + t] = d * rsqrtf(var + EPS_LN) * g[t] + be[t];
}

// ---------------- launch ----------------
static inline void* symraw(const void* s) {
    void* p = nullptr;
    cudaGetSymbolAddress(&p, s);
    return p;
}

extern "C" void kernel_launch(void* const* d_in, const int* in_sizes, int n_in,
                              void* d_out, int out_size)
{
    (void)in_sizes; (void)n_in; (void)out_size;
    const float* Le    = (const float*)d_in[0];
    const float* Me    = (const float*)d_in[1];
    const float* Pe    = (const float*)d_in[2];
    const int*   maskL = (const int*)  d_in[3];
    const int*   maskP = (const int*)  d_in[4];
    const float *Wl  = (const float*)d_in[5],  *bl  = (const float*)d_in[6];
    const float *Wm  = (const float*)d_in[7],  *bm  = (const float*)d_in[8];
    const float *Wp  = (const float*)d_in[9],  *bp  = (const float*)d_in[10];
    const float *Wql = (const float*)d_in[11], *bql = (const float*)d_in[12];
    const float *Wkl = (const float*)d_in[13], *bkl = (const float*)d_in[14];
    const float *Wvl = (const float*)d_in[15], *bvl = (const float*)d_in[16];
    const float *Wqp = (const float*)d_in[17], *bqp = (const float*)d_in[18];
    const float *Wkp = (const float*)d_in[19], *bkp = (const float*)d_in[20];
    const float *Wvp = (const float*)d_in[21], *bvp = (const float*)d_in[22];
    const float *Wml = (const float*)d_in[23], *bml = (const float*)d_in[24];
    const float *Wmp = (const float*)d_in[25], *bmp = (const float*)d_in[26];
    const float *g1  = (const float*)d_in[27], *be1 = (const float*)d_in[28];
    const float *g2  = (const float*)d_in[29], *be2 = (const float*)d_in[30];

    float* preL = (float*)symraw(g_preL);
    float* preP = (float*)symraw(g_preP);

    __half* hWcat  = (__half*)symraw(g_hWcat);
    float*  biascat= (float*) symraw(g_biascat);
    __half* hWmlT  = (__half*)symraw(g_hWmlT);
    __half* hWmpT  = (__half*)symraw(g_hWmpT);

    __half* hEmb  = (__half*)symraw(g_hEmb);
    __half* hMe   = (__half*)symraw(g_hMe);
    __half* hmt   = (__half*)symraw(g_hmt);
    __half* hltpt = (__half*)symraw(g_hltpt);
    __half* hQlp  = (__half*)symraw(g_hQlp);
    __half* hKm   = (__half*)symraw(g_hKm);
    __half* hVTm  = (__half*)symraw(g_hVTm);
    __half* haw   = (__half*)symraw(g_haw);
    __half* hawT  = (__half*)symraw(g_hawT);
    __half* hctx  = (__half*)symraw(g_hctx);
    __half* hctxT = (__half*)symraw(g_hctxT);
    __half* hTT   = (__half*)symraw(g_hTT);
    __half* hfin  = (__half*)symraw(g_hfin);

    const float scale = 0.125f;   // 1/sqrt(DH)
    const float invH  = 0.125f;   // 1/H

    const long ES = (long)L_DIM * HID;     // embedding-sized stride
    const long AS = (long)L_DIM * HK;      // attention-map stride

    // 0) inputs + weights -> fp16 (weights transposed to [N][K], packed)
    conv_k<<<(L_DIM * HID / 4 + 255) / 256, 256>>>((const float4*)Le, (__half2*)hEmb, L_DIM * HID / 4);
    conv_k<<<(P_DIM * HID / 4 + 255) / 256, 256>>>((const float4*)Pe, (__half2*)(hEmb + ES), P_DIM * HID / 4);
    conv_k<<<(M_DIM * HID / 4 + 255) / 256, 256>>>((const float4*)Me, (__half2*)hMe, M_DIM * HID / 4);
    {
        dim3 gw(HID / 32, HID / 32);
        tconv_f2h_k<<<gw, 256>>>(Wl,  hWcat + 0 * WSQ, HID, HID);
        tconv_f2h_k<<<gw, 256>>>(Wp,  hWcat + 1 * WSQ, HID, HID);
        tconv_f2h_k<<<gw, 256>>>(Wm,  hWcat + 2 * WSQ, HID, HID);
        tconv_f2h_k<<<gw, 256>>>(Wql, hWcat + 3 * WSQ, HID, HID);
        tconv_f2h_k<<<gw, 256>>>(Wqp, hWcat + 4 * WSQ, HID, HID);
        tconv_f2h_k<<<gw, 256>>>(Wkl, hWcat + 5 * WSQ, HID, HID);
        tconv_f2h_k<<<gw, 256>>>(Wkp, hWcat + 6 * WSQ, HID, HID);
        tconv_f2h_k<<<gw, 256>>>(Wvl, hWcat + 7 * WSQ, HID, HID);
        tconv_f2h_k<<<gw, 256>>>(Wvp, hWcat + 8 * WSQ, HID, HID);
        dim3 gw2(DHALF / 32, 2 * HID / 32);
        tconv_f2h_k<<<gw2, 256>>>(Wml, hWmlT, 2 * HID, DHALF);
        tconv_f2h_k<<<gw2, 256>>>(Wmp, hWmpT, 2 * HID, DHALF);
    }
    pack_bias_k<<<1, 512>>>(biascat, bl, bp, bm, bql, bqp, bkl, bkp, bvl, bvp);

    // 1) {Le,Pe} @ {Wl,Wp} -> {lt,pt}   (z=2)
    hgemm<128,32,false,0,true,1>(hEmb, nullptr, HID, ES, hWcat, HID, WSQ,
                                 nullptr, hltpt, HID, ES, nullptr, nullptr, 0, 0,
                                 biascat, HID, 1.f, L_DIM, HID, HID, 2);
    // 2) Me @ Wm -> mt
    hgemm<128,32,false,0,true,1>(hMe, nullptr, HID, 0, hWcat + 2 * WSQ, HID, 0,
                                 nullptr, hmt, HID, 0, nullptr, nullptr, 0, 0,
                                 biascat + 2 * HID, 0, 1.f, M_DIM, HID, HID, 1);
    // 3) {lt,pt} @ {Wql,Wqp} -> {Ql,Qp}  (z=2)
    hgemm<128,32,false,0,true,1>(hltpt, nullptr, HID, ES, hWcat + 3 * WSQ, HID, WSQ,
                                 nullptr, hQlp, HID, ES, nullptr, nullptr, 0, 0,
                                 biascat + 3 * HID, HID, 1.f, L_DIM, HID, HID, 2);
    // 4) mt @ {Wkl,Wkp} -> {Kl,Kp}       (z=2, A shared)
    hgemm<128,32,false,0,true,1>(hmt, nullptr, HID, 0, hWcat + 5 * WSQ, HID, WSQ,
                                 nullptr, hKm, HID, (long)M_DIM * HID, nullptr, nullptr, 0, 0,
                                 biascat + 5 * HID, HID, 1.f, M_DIM, HID, HID, 2);
    // 5) {Wvl,Wvp}^T-trick: V^T = W^T @ mt^T  (z=2, row bias)
    hgemm<128,32,false,0,true,2>(hWcat + 7 * WSQ, nullptr, HID, WSQ, hmt, HID, 0,
                                 nullptr, hVTm, M_DIM, (long)HID * M_DIM, nullptr, nullptr, 0, 0,
                                 biascat + 7 * HID, HID, 1.f, HID, M_DIM, HID, 2);

    // 6) attention scores (z=8 heads) -> fp16 score buffers
    hgemm<128,32,false,0,true,0>(hQlp, nullptr, HID, DH, hKm, HID, DH,
                                 nullptr, haw, HK, M_DIM, nullptr, nullptr, 0, 0,
                                 nullptr, 0, scale, L_DIM, M_DIM, DH, NH);
    hgemm<128,32,false,0,true,0>(hQlp + ES, nullptr, HID, DH, hKm + (long)M_DIM * HID, HID, DH,
                                 nullptr, haw + AS, HK, M_DIM, nullptr, nullptr, 0, 0,
                                 nullptr, 0, scale, P_DIM, M_DIM, DH, NH);

    // 7) fused masked softmax + aw transpose (p-first layout in hawT)
    cudaFuncSetAttribute(softmaxT_k, cudaFuncAttributeMaxDynamicSharedMemorySize, SMT_BYTES);
    softmaxT_k<<<dim3(L_DIM / 32, NH), 256, SMT_BYTES>>>(haw, hawT + (size_t)HK * L_DIM, maskL, L_DIM);
    softmaxT_k<<<dim3(P_DIM / 32, NH), 256, SMT_BYTES>>>(haw + AS, hawT, maskP, P_DIM);

    // 8) context (BN=64, NT vs V^T, relu) -> fp16 ctx
    hgemm<64,32,true,0,true,0>(haw, nullptr, HK, M_DIM, hVTm, M_DIM, (long)DH * M_DIM,
                               nullptr, hctx, HID, DH, nullptr, nullptr, 0, 0,
                               nullptr, 0, 1.f, L_DIM, DH, M_DIM, NH);
    hgemm<64,32,true,0,true,0>(haw + AS, nullptr, HK, M_DIM, hVTm + (long)HID * M_DIM, M_DIM, (long)DH * M_DIM,
                               nullptr, hctx + ES, HID, DH, nullptr, nullptr, 0, 0,
                               nullptr, 0, 1.f, P_DIM, DH, M_DIM, NH);

    // 9) ctx transposes for the mutual chain (p first)
    tconv_h2h_k<<<dim3(HID / 32, P_DIM / 32), 256>>>(hctx + ES, hctxT, P_DIM, HID);
    tconv_h2h_k<<<dim3(HID / 32, L_DIM / 32), 256>>>(hctx, hctxT + (long)HID * L_DIM, L_DIM, HID);

    // 10) T-GEMMs batched (z=2): TpT = ctxp^T @ awp ; TlT = ctxl^T @ awl
    hgemm<128,32,false,0,true,0>(hctxT, nullptr, P_DIM, (long)HID * P_DIM, hawT, P_DIM, (long)HK * P_DIM,
                                 nullptr, hTT, HK, (long)HID * HK, nullptr, nullptr, 0, 0,
                                 nullptr, 0, 1.f, HID, HK, P_DIM, 2);
    // 11) fin batched (z=2): finl = ctxl + (1/H) awl @ TpT^T ; finp = ctxp + (1/H) awp @ TlT^T
    hgemm<128,32,false,2,true,0>(haw, nullptr, HK, AS, hTT, HK, (long)HID * HK,
                                 nullptr, hfin, HID, ES, nullptr, hctx, HID, ES,
                                 nullptr, 0, invH, L_DIM, HID, HK, 2);

    // 12) final linears: single K=1024 GEMM each via dual-A (concat semantics)
    hgemm<64,32,false,0,false,1,true>(hltpt, hfin, HID, 0, hWmlT, 2 * HID, 0,
                                      preL, nullptr, DHALF, 0, nullptr, nullptr, 0, 0,
                                      bml, 0, 1.f, L_DIM, DHALF, 2 * HID, 1);
    hgemm<64,32,false,0,false,1,true>(hfin + ES, hltpt + ES, HID, 0, hWmpT, 2 * HID, 0,
                                      preP, nullptr, DHALF, 0, nullptr, nullptr, 0, 0,
                                      bmp, 0, 1.f, P_DIM, DHALF, 2 * HID, 1);

    // 13) layernorms -> output
    float* out = (float*)d_out;
    ln_k<<<L_DIM, 256>>>(preL, g1, be1, out);
    ln_k<<<P_DIM, 256>>>(preP, g2, be2, out + (size_t)L_DIM * DHALF);
}

// round 15
// speedup vs baseline: 1.5855x; 1.0201x over previous
#include <cuda_runtime.h>
#include <cuda_fp16.h>
#include <math.h>
#include <stdint.h>

// Problem constants
#define L_DIM 4096
#define M_DIM 1024
#define P_DIM 4096
#define HID   512
#define NH    8
#define DH    64
#define HK    (NH * M_DIM)   // 8192 flattened (h, m)
#define DHALF 256
#define EPS_LN 1e-5f
#define WSQ   (HID * HID)

// ---------------- scratch (static device globals; no allocation) ----------------
__device__ float g_preL[L_DIM * DHALF];
__device__ float g_preP[P_DIM * DHALF];

// packed fp16 weights (transposed [N][K]) and packed biases
// slots: 0 Wl, 1 Wp, 2 Wm, 3 Wql, 4 Wqp, 5 Wkl, 6 Wkp, 7 Wvl, 8 Wvp
__device__ __half g_hWcat[9 * WSQ];
__device__ float  g_biascat[9 * HID];
__device__ __half g_hWmlT[DHALF * 2 * HID];   // [256][1024]
__device__ __half g_hWmpT[DHALF * 2 * HID];

// fp16 activations (L/P pairs contiguous for z-batching)
__device__ __half g_hEmb [2 * L_DIM * HID];            // Le, Pe
__device__ __half g_hMe  [M_DIM * HID];
__device__ __half g_hmt  [M_DIM * HID];
__device__ __half g_hltpt[2 * L_DIM * HID];            // lt, pt
__device__ __half g_hQlp [2 * L_DIM * HID];            // Ql, Qp
__device__ __half g_hKm  [2 * M_DIM * HID];            // Kl, Kp
__device__ __half g_hVTm [2 * HID * M_DIM];            // VlT, VpT  ([HID][M])
__device__ __half g_haw  [(size_t)2 * L_DIM * HK];     // awl, awp
__device__ __half g_hawT [(size_t)2 * HK * L_DIM];     // awpT, awlT  (note p first)
__device__ __half g_hctx [2 * L_DIM * HID];            // ctxl, ctxp
__device__ __half g_hctxT[2 * HID * L_DIM];            // ctxpT, ctxlT (p first)
__device__ __half g_hTT  [2 * HID * HK];               // TpT, TlT
__device__ __half g_hfin [2 * L_DIM * HID];            // finl, finp

// ================= fp16 tensor-core GEMM (mma.sync NT, 3-stage, strided/batched) =================
// C[M,N] = alpha * A[M,K](f16, ld=lda) @ B[N,K](f16, ld=ldb)^T  (+bias) (+Cadd) (relu)
// WTN: warp tile N (32). CADDM: 0 none, 1 f32 Cadd, 2 f16 Cadd.
// BIASM: 0 none, 1 per-col, 2 per-row.
// DUALA: A supplies K rows [0,Kd/2) and A2 supplies [Kd/2,Kd) (both ld=lda).
// TROUT: additionally write transposed fp16 output ChT[(z*? + col)*ldT + row].
// Requires M%128==0, N%BN==0, K%32==0, K>=64 (all call sites exact).
#define HPAD 40

__device__ __forceinline__ uint32_t smem_u32(const void* p) {
    return (uint32_t)__cvta_generic_to_shared(p);
}

template<int BN, int WTN, bool RELU, int CADDM, bool OUTF16, int BIASM, bool DUALA, bool TROUT>
__global__ void __launch_bounds__(256)
hgemm_k(const __half* __restrict__ A, const __half* __restrict__ A2, int lda, long sA,
        const __half* __restrict__ B, int ldb, long sB,
        float* __restrict__ C, __half* __restrict__ Ch, int ldc, long sC,
        const float* __restrict__ CaddF, const __half* __restrict__ CaddH,
        int ldadd, long sAdd,
        const float* __restrict__ bias, long sBias,
        __half* __restrict__ ChT, int ldT, long sCT,
        float alpha, int Md, int Nd, int Kd)
{
    constexpr int BM = 128;
    constexpr int WN = BN / WTN;         // warps along N
    constexpr int WM = 8 / WN;           // warps along M
    constexpr int MI = BM / (WM * 16);   // m16 fragments per warp
    constexpr int NI = WTN / 8;          // n8 fragments per warp

    extern __shared__ __half hsm[];
    __half* sAb = hsm;                   // 3 stages x BM*HPAD
    __half* sBb = hsm + 3 * BM * HPAD;   // 3 stages x BN*HPAD

    const int tid  = threadIdx.x;
    const int wid  = tid >> 5, lane = tid & 31;
    const int wr   = wid / WN, wc = wid % WN;
    const int m0   = blockIdx.y * BM;
    const int n0   = blockIdx.x * BN;
    const long z   = blockIdx.z;

    A += z * sA;
    B += z * sB;

    float acc[MI][NI][4];
#pragma unroll
    for (int mi = 0; mi < MI; mi++)
#pragma unroll
        for (int ni = 0; ni < NI; ni++)
#pragma unroll
            for (int q = 0; q < 4; q++) acc[mi][ni][q] = 0.f;

    const int KT  = Kd / 32;
    const int KTH = Kd / 64;             // DUALA switch point

    auto load_stage = [&](int s, int kt) {
        __half* sa = sAb + s * BM * HPAD;
        __half* sb = sBb + s * BN * HPAD;
        const __half* Ause = A;
        int ktA = kt;
        if (DUALA && kt >= KTH) { Ause = A2; ktA = kt - KTH; }
#pragma unroll
        for (int i = 0; i < (BM * 4) / 256; i++) {
            int idx = tid + i * 256;
            int r = idx >> 2, u = idx & 3;
            const __half* g = Ause + (size_t)(m0 + r) * lda + ktA * 32 + u * 8;
            asm volatile("cp.async.ca.shared.global [%0], [%1], 16;\n"
                         :: "r"(smem_u32(&sa[r * HPAD + u * 8])), "l"(g));
        }
#pragma unroll
        for (int i = 0; i < (BN * 4) / 256; i++) {
            int idx = tid + i * 256;
            int r = idx >> 2, u = idx & 3;
            const __half* g = B + (size_t)(n0 + r) * ldb + kt * 32 + u * 8;
            asm volatile("cp.async.ca.shared.global [%0], [%1], 16;\n"
                         :: "r"(smem_u32(&sb[r * HPAD + u * 8])), "l"(g));
        }
        asm volatile("cp.async.commit_group;\n");
    };

    load_stage(0, 0);
    load_stage(1, 1);        // KT >= 2 at every call site

    for (int kt = 0; kt < KT; kt++) {
        const int s = kt % 3;
        if (kt + 1 < KT) { asm volatile("cp.async.wait_group 1;\n" ::: "memory"); }
        else             { asm volatile("cp.async.wait_group 0;\n" ::: "memory"); }
        __syncthreads();
        if (kt + 2 < KT) load_stage((kt + 2) % 3, kt + 2);

        const __half* sa = sAb + s * BM * HPAD;
        const __half* sb = sBb + s * BN * HPAD;

#pragma unroll
        for (int ks = 0; ks < 2; ks++) {
            uint32_t a[MI][4], b[NI][2];
#pragma unroll
            for (int mi = 0; mi < MI; mi++) {
                int row = wr * (MI * 16) + mi * 16 + (lane & 15);
                int col = ks * 16 + (lane >> 4) * 8;
                uint32_t addr = smem_u32(&sa[row * HPAD + col]);
                asm volatile("ldmatrix.sync.aligned.m8n8.x4.shared.b16 {%0,%1,%2,%3}, [%4];\n"
                             : "=r"(a[mi][0]), "=r"(a[mi][1]), "=r"(a[mi][2]), "=r"(a[mi][3])
                             : "r"(addr));
            }
#pragma unroll
            for (int j = 0; j < NI / 2; j++) {
                int n   = wc * WTN + j * 16 + (lane & 7) + ((lane >> 4) << 3);
                int col = ks * 16 + ((lane >> 3) & 1) * 8;
                uint32_t addr = smem_u32(&sb[n * HPAD + col]);
                uint32_t r0, r1, r2, r3;
                asm volatile("ldmatrix.sync.aligned.m8n8.x4.shared.b16 {%0,%1,%2,%3}, [%4];\n"
                             : "=r"(r0), "=r"(r1), "=r"(r2), "=r"(r3) : "r"(addr));
                b[2 * j][0] = r0; b[2 * j][1] = r1;
                b[2 * j + 1][0] = r2; b[2 * j + 1][1] = r3;
            }
#pragma unroll
            for (int mi = 0; mi < MI; mi++)
#pragma unroll
                for (int ni = 0; ni < NI; ni++)
                    asm volatile(
                        "mma.sync.aligned.m16n8k16.row.col.f32.f16.f16.f32 "
                        "{%0,%1,%2,%3}, {%4,%5,%6,%7}, {%8,%9}, {%0,%1,%2,%3};\n"
                        : "+f"(acc[mi][ni][0]), "+f"(acc[mi][ni][1]),
                          "+f"(acc[mi][ni][2]), "+f"(acc[mi][ni][3])
                        : "r"(a[mi][0]), "r"(a[mi][1]), "r"(a[mi][2]), "r"(a[mi][3]),
                          "r"(b[ni][0]), "r"(b[ni][1]));
        }
    }
    __syncthreads();

    // epilogue
    const float* bz = bias + z * sBias;
#pragma unroll
    for (int mi = 0; mi < MI; mi++) {
        int row = m0 + wr * (MI * 16) + mi * 16 + (lane >> 2);
#pragma unroll
        for (int ni = 0; ni < NI; ni++) {
            int col = n0 + wc * WTN + ni * 8 + (lane & 3) * 2;
            float2 lo = make_float2(acc[mi][ni][0] * alpha, acc[mi][ni][1] * alpha);
            float2 hi = make_float2(acc[mi][ni][2] * alpha, acc[mi][ni][3] * alpha);
            if (BIASM == 1) {
                float b0 = bz[col], b1 = bz[col + 1];
                lo.x += b0; lo.y += b1; hi.x += b0; hi.y += b1;
            }
            if (BIASM == 2) {
                float br = bz[row], br8 = bz[row + 8];
                lo.x += br; lo.y += br; hi.x += br8; hi.y += br8;
            }
            if (CADDM == 1) {
                const float* ca = CaddF + z * sAdd;
                float2 c0 = *(const float2*)&ca[(size_t)row * ldadd + col];
                float2 c1 = *(const float2*)&ca[(size_t)(row + 8) * ldadd + col];
                lo.x += c0.x; lo.y += c0.y;
                hi.x += c1.x; hi.y += c1.y;
            }
            if (CADDM == 2) {
                const __half* ca = CaddH + z * sAdd;
                float2 c0 = __half22float2(*(const __half2*)&ca[(size_t)row * ldadd + col]);
                float2 c1 = __half22float2(*(const __half2*)&ca[(size_t)(row + 8) * ldadd + col]);
                lo.x += c0.x; lo.y += c0.y;
                hi.x += c1.x; hi.y += c1.y;
            }
            if (RELU) {
                lo.x = fmaxf(lo.x, 0.f); lo.y = fmaxf(lo.y, 0.f);
                hi.x = fmaxf(hi.x, 0.f); hi.y = fmaxf(hi.y, 0.f);
            }
            if (OUTF16) {
                __half* co = Ch + z * sC;
                __half2 h2lo = __floats2half2_rn(lo.x, lo.y);
                __half2 h2hi = __floats2half2_rn(hi.x, hi.y);
                *(__half2*)&co[(size_t)row * ldc + col]       = h2lo;
                *(__half2*)&co[(size_t)(row + 8) * ldc + col] = h2hi;
                if (TROUT) {
                    __half* ct = ChT + z * sCT;
                    ct[(size_t)col * ldT + row]           = __low2half(h2lo);
                    ct[(size_t)(col + 1) * ldT + row]     = __high2half(h2lo);
                    ct[(size_t)col * ldT + row + 8]       = __low2half(h2hi);
                    ct[(size_t)(col + 1) * ldT + row + 8] = __high2half(h2hi);
                }
            } else {
                float* co = C + z * sC;
                *(float2*)&co[(size_t)row * ldc + col]       = lo;
                *(float2*)&co[(size_t)(row + 8) * ldc + col] = hi;
            }
        }
    }
}

template<int BN, int WTN, bool RELU, int CADDM, bool OUTF16, int BIASM, bool DUALA = false, bool TROUT = false>
static inline void hgemm(const __half* A, const __half* A2, int lda, long sA,
                         const __half* B, int ldb, long sB,
                         float* C, __half* Ch, int ldc, long sC,
                         const float* CaddF, const __half* CaddH, int ldadd, long sAdd,
                         const float* bias, long sBias, float alpha,
                         int Md, int Nd, int Kd, int batch,
                         __half* ChT = nullptr, int ldT = 0, long sCT = 0)
{
    constexpr int SMEM = 3 * (128 + BN) * HPAD * 2;
    cudaFuncSetAttribute(hgemm_k<BN, WTN, RELU, CADDM, OUTF16, BIASM, DUALA, TROUT>,
                         cudaFuncAttributeMaxDynamicSharedMemorySize, SMEM);
    dim3 grid(Nd / BN, Md / 128, batch);
    hgemm_k<BN, WTN, RELU, CADDM, OUTF16, BIASM, DUALA, TROUT><<<grid, 256, SMEM>>>(
        A, A2, lda, sA, B, ldb, sB, C, Ch, ldc, sC, CaddF, CaddH, ldadd, sAdd,
        bias, sBias, ChT, ldT, sCT, alpha, Md, Nd, Kd);
}

// ---------------- conversions ----------------
__global__ void __launch_bounds__(256)
conv_k(const float4* __restrict__ in, __half2* __restrict__ out, int n4)
{
    int i = blockIdx.x * 256 + threadIdx.x;
    if (i < n4) {
        float4 v = in[i];
        out[2 * i]     = __floats2half2_rn(v.x, v.y);
        out[2 * i + 1] = __floats2half2_rn(v.z, v.w);
    }
}

// batched transpose of nine 512x512 f32 weights -> packed fp16 [N][K] slots
struct WPtr9 { const float* s[9]; };
__global__ void __launch_bounds__(256)
tconv9_k(WPtr9 w, __half* __restrict__ out)
{
    __shared__ float t[32][33];
    const float* in = w.s[blockIdx.z];
    __half* o = out + (size_t)blockIdx.z * WSQ;
    int c0 = blockIdx.x * 32, r0 = blockIdx.y * 32;
    int x = threadIdx.x & 31, y = threadIdx.x >> 5;
#pragma unroll
    for (int j = 0; j < 32; j += 8)
        t[y + j][x] = in[(size_t)(r0 + y + j) * HID + c0 + x];
    __syncthreads();
#pragma unroll
    for (int j = 0; j < 32; j += 8)
        o[(size_t)(c0 + y + j) * HID + r0 + x] = __float2half(t[x][y + j]);
}

// batched transpose of the two [1024,256] f32 final weights -> [256][1024] fp16
struct WPtr2 { const float* s[2]; __half* d[2]; };
__global__ void __launch_bounds__(256)
tconv2_k(WPtr2 w)
{
    __shared__ float t[32][33];
    const float* in = w.s[blockIdx.z];
    __half* o = w.d[blockIdx.z];
    int c0 = blockIdx.x * 32, r0 = blockIdx.y * 32;
    int x = threadIdx.x & 31, y = threadIdx.x >> 5;
#pragma unroll
    for (int j = 0; j < 32; j += 8)
        t[y + j][x] = in[(size_t)(r0 + y + j) * DHALF + c0 + x];
    __syncthreads();
#pragma unroll
    for (int j = 0; j < 32; j += 8)
        o[(size_t)(c0 + y + j) * (2 * HID) + r0 + x] = __float2half(t[x][y + j]);
}

// pack 9 bias vectors (512 each) into one contiguous buffer
__global__ void __launch_bounds__(512)
pack_bias_k(float* __restrict__ dst,
            const float* b0, const float* b1, const float* b2,
            const float* b3, const float* b4, const float* b5,
            const float* b6, const float* b7, const float* b8)
{
    int t = threadIdx.x;
    dst[0 * HID + t] = b0[t];
    dst[1 * HID + t] = b1[t];
    dst[2 * HID + t] = b2[t];
    dst[3 * HID + t] = b3[t];
    dst[4 * HID + t] = b4[t];
    dst[5 * HID + t] = b5[t];
    dst[6 * HID + t] = b6[t];
    dst[7 * HID + t] = b7[t];
    dst[8 * HID + t] = b8[t];
}

// ---------------- reductions ----------------
__device__ __forceinline__ float warpRedMax(float v) {
#pragma unroll
    for (int o = 16; o > 0; o >>= 1) v = fmaxf(v, __shfl_xor_sync(0xffffffffu, v, o));
    return v;
}
__device__ __forceinline__ float warpRedSum(float v) {
#pragma unroll
    for (int o = 16; o > 0; o >>= 1) v += __shfl_xor_sync(0xffffffffu, v, o);
    return v;
}
__device__ __forceinline__ float blockSum256(float v, float* red) {
    int lane = threadIdx.x & 31, w = threadIdx.x >> 5;
    v = warpRedSum(v);
    if (lane == 0) red[w] = v;
    __syncthreads();
    float r = 0.f;
#pragma unroll
    for (int i = 0; i < 8; i++) r += red[i];
    __syncthreads();
    return r;
}

// ---------------- fused masked softmax + transpose (fp16) ----------------
// Block: 32 rows (l) x 1024 (m) of head h. Normalizes in place into S and
// writes the transpose into ST[(h*M + m) * R + l].
#define SMT_PITCH 1026
#define SMT_BYTES (32 * SMT_PITCH * 2)

__global__ void __launch_bounds__(256)
softmaxT_k(__half* __restrict__ S, __half* __restrict__ ST,
           const int* __restrict__ mask, int R)
{
    extern __shared__ __half sm[];
    const int h  = blockIdx.y;
    const int l0 = blockIdx.x * 32;
    const int wid = threadIdx.x >> 5, lane = threadIdx.x & 31;

#pragma unroll 1
    for (int rr = 0; rr < 4; rr++) {
        const int row = rr * 8 + wid;
        const int l = l0 + row;
        const __half2* src = (const __half2*)(S + (size_t)l * HK + (size_t)h * M_DIM);
        const int2*    m2  = (const int2*)(mask + (size_t)l * M_DIM);

        float2 v[16];
        float mx = -3.4e38f;
#pragma unroll
        for (int i = 0; i < 16; i++) {
            float2 f = __half22float2(src[lane + i * 32]);
            int2  mm = m2[lane + i * 32];
            f.x = (mm.x != 0) ? f.x : -1e9f;
            f.y = (mm.y != 0) ? f.y : -1e9f;
            v[i] = f;
            mx = fmaxf(mx, fmaxf(f.x, f.y));
        }
        mx = warpRedMax(mx);
        float sum = 0.f;
#pragma unroll
        for (int i = 0; i < 16; i++) {
            v[i].x = __expf(v[i].x - mx);
            v[i].y = __expf(v[i].y - mx);
            sum += v[i].x + v[i].y;
        }
        sum = warpRedSum(sum);
        float inv = __frcp_rn(sum);

        __half2* srow = (__half2*)(sm + row * SMT_PITCH);
#pragma unroll
        for (int i = 0; i < 16; i++)
            srow[lane + i * 32] = __floats2half2_rn(v[i].x * inv, v[i].y * inv);
    }
    __syncthreads();

    for (int idx = threadIdx.x; idx < 32 * 512; idx += 256) {
        int row = idx >> 9, c2 = idx & 511;
        __half2 hv = ((const __half2*)(sm + row * SMT_PITCH))[c2];
        ((__half2*)(S + (size_t)(l0 + row) * HK + (size_t)h * M_DIM))[c2] = hv;
    }
    for (int idx = threadIdx.x; idx < 1024 * 16; idx += 256) {
        int m = idx >> 4, lp = idx & 15;
        __half a = sm[(2 * lp)     * SMT_PITCH + m];
        __half b = sm[(2 * lp + 1) * SMT_PITCH + m];
        ((__half2*)(ST + (size_t)(h * M_DIM + m) * R + l0))[lp] = __halves2half2(a, b);
    }
}

// ---------------- layernorm ----------------
__global__ void __launch_bounds__(256)
ln_k(const float* __restrict__ x, const float* __restrict__ g, const float* __restrict__ be,
     float* __restrict__ out)
{
    __shared__ float red[8];
    const int r = blockIdx.x, t = threadIdx.x;
    float v = x[r * 256 + t];
    float mean = blockSum256(v, red) * (1.f / 256.f);
    float d = v - mean;
    float var = blockSum256(d * d, red) * (1.f / 256.f);
    out[r * 256 + t] = d * rsqrtf(var + EPS_LN) * g[t] + be[t];
}

// ---------------- launch ----------------
static inline void* symraw(const void* s) {
    void* p = nullptr;
    cudaGetSymbolAddress(&p, s);
    return p;
}

extern "C" void kernel_launch(void* const* d_in, const int* in_sizes, int n_in,
                              void* d_out, int out_size)
{
    (void)in_sizes; (void)n_in; (void)out_size;
    const float* Le    = (const float*)d_in[0];
    const float* Me    = (const float*)d_in[1];
    const float* Pe    = (const float*)d_in[2];
    const int*   maskL = (const int*)  d_in[3];
    const int*   maskP = (const int*)  d_in[4];
    const float *Wl  = (const float*)d_in[5],  *bl  = (const float*)d_in[6];
    const float *Wm  = (const float*)d_in[7],  *bm  = (const float*)d_in[8];
    const float *Wp  = (const float*)d_in[9],  *bp  = (const float*)d_in[10];
    const float *Wql = (const float*)d_in[11], *bql = (const float*)d_in[12];
    const float *Wkl = (const float*)d_in[13], *bkl = (const float*)d_in[14];
    const float *Wvl = (const float*)d_in[15], *bvl = (const float*)d_in[16];
    const float *Wqp = (const float*)d_in[17], *bqp = (const float*)d_in[18];
    const float *Wkp = (const float*)d_in[19], *bkp = (const float*)d_in[20];
    const float *Wvp = (const float*)d_in[21], *bvp = (const float*)d_in[22];
    const float *Wml = (const float*)d_in[23], *bml = (const float*)d_in[24];
    const float *Wmp = (const float*)d_in[25], *bmp = (const float*)d_in[26];
    const float *g1  = (const float*)d_in[27], *be1 = (const float*)d_in[28];
    const float *g2  = (const float*)d_in[29], *be2 = (const float*)d_in[30];

    float* preL = (float*)symraw(g_preL);
    float* preP = (float*)symraw(g_preP);

    __half* hWcat  = (__half*)symraw(g_hWcat);
    float*  biascat= (float*) symraw(g_biascat);
    __half* hWmlT  = (__half*)symraw(g_hWmlT);
    __half* hWmpT  = (__half*)symraw(g_hWmpT);

    __half* hEmb  = (__half*)symraw(g_hEmb);
    __half* hMe   = (__half*)symraw(g_hMe);
    __half* hmt   = (__half*)symraw(g_hmt);
    __half* hltpt = (__half*)symraw(g_hltpt);
    __half* hQlp  = (__half*)symraw(g_hQlp);
    __half* hKm   = (__half*)symraw(g_hKm);
    __half* hVTm  = (__half*)symraw(g_hVTm);
    __half* haw   = (__half*)symraw(g_haw);
    __half* hawT  = (__half*)symraw(g_hawT);
    __half* hctx  = (__half*)symraw(g_hctx);
    __half* hctxT = (__half*)symraw(g_hctxT);
    __half* hTT   = (__half*)symraw(g_hTT);
    __half* hfin  = (__half*)symraw(g_hfin);

    const float scale = 0.125f;   // 1/sqrt(DH)
    const float invH  = 0.125f;   // 1/H

    const long ES = (long)L_DIM * HID;     // embedding-sized stride
    const long AS = (long)L_DIM * HK;      // attention-map stride

    // 0) inputs + weights -> fp16 (weights transposed to [N][K], packed/batched)
    conv_k<<<(L_DIM * HID / 4 + 255) / 256, 256>>>((const float4*)Le, (__half2*)hEmb, L_DIM * HID / 4);
    conv_k<<<(P_DIM * HID / 4 + 255) / 256, 256>>>((const float4*)Pe, (__half2*)(hEmb + ES), P_DIM * HID / 4);
    conv_k<<<(M_DIM * HID / 4 + 255) / 256, 256>>>((const float4*)Me, (__half2*)hMe, M_DIM * HID / 4);
    {
        WPtr9 w9;
        w9.s[0] = Wl;  w9.s[1] = Wp;  w9.s[2] = Wm;
        w9.s[3] = Wql; w9.s[4] = Wqp; w9.s[5] = Wkl;
        w9.s[6] = Wkp; w9.s[7] = Wvl; w9.s[8] = Wvp;
        tconv9_k<<<dim3(HID / 32, HID / 32, 9), 256>>>(w9, hWcat);
        WPtr2 w2;
        w2.s[0] = Wml; w2.s[1] = Wmp;
        w2.d[0] = hWmlT; w2.d[1] = hWmpT;
        tconv2_k<<<dim3(DHALF / 32, 2 * HID / 32, 2), 256>>>(w2);
    }
    pack_bias_k<<<1, 512>>>(biascat, bl, bp, bm, bql, bqp, bkl, bkp, bvl, bvp);

    // 1) {Le,Pe} @ {Wl,Wp} -> {lt,pt}   (z=2)
    hgemm<128,32,false,0,true,1>(hEmb, nullptr, HID, ES, hWcat, HID, WSQ,
                                 nullptr, hltpt, HID, ES, nullptr, nullptr, 0, 0,
                                 biascat, HID, 1.f, L_DIM, HID, HID, 2);
    // 2) Me @ Wm -> mt
    hgemm<128,32,false,0,true,1>(hMe, nullptr, HID, 0, hWcat + 2 * WSQ, HID, 0,
                                 nullptr, hmt, HID, 0, nullptr, nullptr, 0, 0,
                                 biascat + 2 * HID, 0, 1.f, M_DIM, HID, HID, 1);
    // 3) {lt,pt} @ {Wql,Wqp} -> {Ql,Qp}  (z=2)
    hgemm<128,32,false,0,true,1>(hltpt, nullptr, HID, ES, hWcat + 3 * WSQ, HID, WSQ,
                                 nullptr, hQlp, HID, ES, nullptr, nullptr, 0, 0,
                                 biascat + 3 * HID, HID, 1.f, L_DIM, HID, HID, 2);
    // 4) mt @ {Wkl,Wkp} -> {Kl,Kp}       (z=2, A shared)
    hgemm<128,32,false,0,true,1>(hmt, nullptr, HID, 0, hWcat + 5 * WSQ, HID, WSQ,
                                 nullptr, hKm, HID, (long)M_DIM * HID, nullptr, nullptr, 0, 0,
                                 biascat + 5 * HID, HID, 1.f, M_DIM, HID, HID, 2);
    // 5) {Wvl,Wvp}^T-trick: V^T = W^T @ mt^T  (z=2, row bias)
    hgemm<128,32,false,0,true,2>(hWcat + 7 * WSQ, nullptr, HID, WSQ, hmt, HID, 0,
                                 nullptr, hVTm, M_DIM, (long)HID * M_DIM, nullptr, nullptr, 0, 0,
                                 biascat + 7 * HID, HID, 1.f, HID, M_DIM, HID, 2);

    // 6) attention scores (z=8 heads) -> fp16 score buffers
    hgemm<128,32,false,0,true,0>(hQlp, nullptr, HID, DH, hKm, HID, DH,
                                 nullptr, haw, HK, M_DIM, nullptr, nullptr, 0, 0,
                                 nullptr, 0, scale, L_DIM, M_DIM, DH, NH);
    hgemm<128,32,false,0,true,0>(hQlp + ES, nullptr, HID, DH, hKm + (long)M_DIM * HID, HID, DH,
                                 nullptr, haw + AS, HK, M_DIM, nullptr, nullptr, 0, 0,
                                 nullptr, 0, scale, P_DIM, M_DIM, DH, NH);

    // 7) fused masked softmax + aw transpose (p-first layout in hawT)
    cudaFuncSetAttribute(softmaxT_k, cudaFuncAttributeMaxDynamicSharedMemorySize, SMT_BYTES);
    softmaxT_k<<<dim3(L_DIM / 32, NH), 256, SMT_BYTES>>>(haw, hawT + (size_t)HK * L_DIM, maskL, L_DIM);
    softmaxT_k<<<dim3(P_DIM / 32, NH), 256, SMT_BYTES>>>(haw + AS, hawT, maskP, P_DIM);

    // 8) context (BN=64, NT vs V^T, relu) -> fp16 ctx + fused transposed output
    hgemm<64,32,true,0,true,0,false,true>(
        haw, nullptr, HK, M_DIM, hVTm, M_DIM, (long)DH * M_DIM,
        nullptr, hctx, HID, DH, nullptr, nullptr, 0, 0,
        nullptr, 0, 1.f, L_DIM, DH, M_DIM, NH,
        hctxT + (long)HID * L_DIM, L_DIM, (long)DH * L_DIM);
    hgemm<64,32,true,0,true,0,false,true>(
        haw + AS, nullptr, HK, M_DIM, hVTm + (long)HID * M_DIM, M_DIM, (long)DH * M_DIM,
        nullptr, hctx + ES, HID, DH, nullptr, nullptr, 0, 0,
        nullptr, 0, 1.f, P_DIM, DH, M_DIM, NH,
        hctxT, P_DIM, (long)DH * P_DIM);

    // 9) T-GEMMs batched (z=2): TpT = ctxp^T @ awp ; TlT = ctxl^T @ awl
    hgemm<128,32,false,0,true,0>(hctxT, nullptr, P_DIM, (long)HID * P_DIM, hawT, P_DIM, (long)HK * P_DIM,
                                 nullptr, hTT, HK, (long)HID * HK, nullptr, nullptr, 0, 0,
                                 nullptr, 0, 1.f, HID, HK, P_DIM, 2);
    // 10) fin batched (z=2): finl = ctxl + (1/H) awl @ TpT^T ; finp = ctxp + (1/H) awp @ TlT^T
    hgemm<128,32,false,2,true,0>(haw, nullptr, HK, AS, hTT, HK, (long)HID * HK,
                                 nullptr, hfin, HID, ES, nullptr, hctx, HID, ES,
                                 nullptr, 0, invH, L_DIM, HID, HK, 2);

    // 11) final linears: single K=1024 GEMM each via dual-A (concat semantics)
    hgemm<64,32,false,0,false,1,true>(hltpt, hfin, HID, 0, hWmlT, 2 * HID, 0,
                                      preL, nullptr, DHALF, 0, nullptr, nullptr, 0, 0,
                                      bml, 0, 1.f, L_DIM, DHALF, 2 * HID, 1);
    hgemm<64,32,false,0,false,1,true>(hfin + ES, hltpt + ES, HID, 0, hWmpT, 2 * HID, 0,
                                      preP, nullptr, DHALF, 0, nullptr, nullptr, 0, 0,
                                      bmp, 0, 1.f, P_DIM, DHALF, 2 * HID, 1);

    // 12) layernorms -> output
    float* out = (float*)d_out;
    ln_k<<<L_DIM, 256>>>(preL, g1, be1, out);
    ln_k<<<P_DIM, 256>>>(preP, g2, be2, out + (size_t)L_DIM * DHALF);
}

// round 16
// speedup vs baseline: 1.6319x; 1.0292x over previous
#include <cuda_runtime.h>
#include <cuda_fp16.h>
#include <math.h>
#include <stdint.h>

// Problem constants
#define L_DIM 4096
#define M_DIM 1024
#define P_DIM 4096
#define HID   512
#define NH    8
#define DH    64
#define HK    (NH * M_DIM)   // 8192 flattened (h, m)
#define DHALF 256
#define EPS_LN 1e-5f
#define WSQ   (HID * HID)

// ---------------- scratch (static device globals; no allocation) ----------------
__device__ float g_preL[L_DIM * DHALF];
__device__ float g_preP[P_DIM * DHALF];

// packed fp16 weights (transposed [N][K]) and packed biases
// slots: 0 Wl, 1 Wp, 2 Wm, 3 Wql, 4 Wqp, 5 Wkl, 6 Wkp, 7 Wvl, 8 Wvp
__device__ __half g_hWcat[9 * WSQ];
__device__ float  g_biascat[9 * HID];
__device__ __half g_hWmlT[DHALF * 2 * HID];   // [256][1024]
__device__ __half g_hWmpT[DHALF * 2 * HID];

// fp16 activations (L/P pairs contiguous for z-batching)
__device__ __half g_hEmb [2 * L_DIM * HID];            // Le, Pe
__device__ __half g_hMe  [M_DIM * HID];
__device__ __half g_hmt  [M_DIM * HID];
__device__ __half g_hltpt[2 * L_DIM * HID];            // lt, pt
__device__ __half g_hQlp [2 * L_DIM * HID];            // Ql, Qp
__device__ __half g_hKm  [2 * M_DIM * HID];            // Kl, Kp
__device__ __half g_hVTm [2 * HID * M_DIM];            // VlT, VpT  ([HID][M])
__device__ __half g_haw  [(size_t)2 * L_DIM * HK];     // awl, awp
__device__ __half g_hawT [(size_t)2 * HK * L_DIM];     // awpT, awlT  (note p first)
__device__ __half g_hctx [2 * L_DIM * HID];            // ctxl, ctxp
__device__ __half g_hctxT[2 * HID * L_DIM];            // ctxpT, ctxlT (p first)
__device__ __half g_hTT  [2 * HID * HK];               // TpT, TlT
__device__ __half g_hfin [2 * L_DIM * HID];            // finl, finp

// ================= fp16 tensor-core GEMM (mma.sync NT, 3-stage, strided/batched) =================
// C[M,N] = alpha * A[M,K](f16, ld=lda) @ B[N,K](f16, ld=ldb)^T  (+bias) (+Cadd) (relu)
// WTN: warp tile N (32). CADDM: 0 none, 1 f32 Cadd, 2 f16 Cadd.
// BIASM: 0 none, 1 per-col, 2 per-row.
// DUALA: A supplies K rows [0,Kd/2) and A2 supplies [Kd/2,Kd) (both ld=lda).
// TROUT: additionally write transposed fp16 output ChT[(z*? + col)*ldT + row].
// Requires M%128==0, N%BN==0, K%32==0, K>=64 (all call sites exact).
#define HPAD 40

__device__ __forceinline__ uint32_t smem_u32(const void* p) {
    return (uint32_t)__cvta_generic_to_shared(p);
}

template<int BN, int WTN, bool RELU, int CADDM, bool OUTF16, int BIASM, bool DUALA, bool TROUT>
__global__ void __launch_bounds__(256, 2)
hgemm_k(const __half* __restrict__ A, const __half* __restrict__ A2, int lda, long sA,
        const __half* __restrict__ B, int ldb, long sB,
        float* __restrict__ C, __half* __restrict__ Ch, int ldc, long sC,
        const float* __restrict__ CaddF, const __half* __restrict__ CaddH,
        int ldadd, long sAdd,
        const float* __restrict__ bias, long sBias,
        __half* __restrict__ ChT, int ldT, long sCT,
        float alpha, int Md, int Nd, int Kd)
{
    constexpr int BM = 128;
    constexpr int WN = BN / WTN;         // warps along N
    constexpr int WM = 8 / WN;           // warps along M
    constexpr int MI = BM / (WM * 16);   // m16 fragments per warp
    constexpr int NI = WTN / 8;          // n8 fragments per warp

    extern __shared__ __half hsm[];
    __half* sAb = hsm;                   // 3 stages x BM*HPAD
    __half* sBb = hsm + 3 * BM * HPAD;   // 3 stages x BN*HPAD

    const int tid  = threadIdx.x;
    const int wid  = tid >> 5, lane = tid & 31;
    const int wr   = wid / WN, wc = wid % WN;
    const int m0   = blockIdx.y * BM;
    const int n0   = blockIdx.x * BN;
    const long z   = blockIdx.z;

    A += z * sA;
    B += z * sB;

    float acc[MI][NI][4];
#pragma unroll
    for (int mi = 0; mi < MI; mi++)
#pragma unroll
        for (int ni = 0; ni < NI; ni++)
#pragma unroll
            for (int q = 0; q < 4; q++) acc[mi][ni][q] = 0.f;

    const int KT  = Kd / 32;
    const int KTH = Kd / 64;             // DUALA switch point

    auto load_stage = [&](int s, int kt) {
        __half* sa = sAb + s * BM * HPAD;
        __half* sb = sBb + s * BN * HPAD;
        const __half* Ause = A;
        int ktA = kt;
        if (DUALA && kt >= KTH) { Ause = A2; ktA = kt - KTH; }
#pragma unroll
        for (int i = 0; i < (BM * 4) / 256; i++) {
            int idx = tid + i * 256;
            int r = idx >> 2, u = idx & 3;
            const __half* g = Ause + (size_t)(m0 + r) * lda + ktA * 32 + u * 8;
            asm volatile("cp.async.ca.shared.global [%0], [%1], 16;\n"
                         :: "r"(smem_u32(&sa[r * HPAD + u * 8])), "l"(g));
        }
#pragma unroll
        for (int i = 0; i < (BN * 4) / 256; i++) {
            int idx = tid + i * 256;
            int r = idx >> 2, u = idx & 3;
            const __half* g = B + (size_t)(n0 + r) * ldb + kt * 32 + u * 8;
            asm volatile("cp.async.ca.shared.global [%0], [%1], 16;\n"
                         :: "r"(smem_u32(&sb[r * HPAD + u * 8])), "l"(g));
        }
        asm volatile("cp.async.commit_group;\n");
    };

    load_stage(0, 0);
    load_stage(1, 1);        // KT >= 2 at every call site

    for (int kt = 0; kt < KT; kt++) {
        const int s = kt % 3;
        if (kt + 1 < KT) { asm volatile("cp.async.wait_group 1;\n" ::: "memory"); }
        else             { asm volatile("cp.async.wait_group 0;\n" ::: "memory"); }
        __syncthreads();
        if (kt + 2 < KT) load_stage((kt + 2) % 3, kt + 2);

        const __half* sa = sAb + s * BM * HPAD;
        const __half* sb = sBb + s * BN * HPAD;

#pragma unroll
        for (int ks = 0; ks < 2; ks++) {
            uint32_t a[MI][4], b[NI][2];
#pragma unroll
            for (int mi = 0; mi < MI; mi++) {
                int row = wr * (MI * 16) + mi * 16 + (lane & 15);
                int col = ks * 16 + (lane >> 4) * 8;
                uint32_t addr = smem_u32(&sa[row * HPAD + col]);
                asm volatile("ldmatrix.sync.aligned.m8n8.x4.shared.b16 {%0,%1,%2,%3}, [%4];\n"
                             : "=r"(a[mi][0]), "=r"(a[mi][1]), "=r"(a[mi][2]), "=r"(a[mi][3])
                             : "r"(addr));
            }
#pragma unroll
            for (int j = 0; j < NI / 2; j++) {
                int n   = wc * WTN + j * 16 + (lane & 7) + ((lane >> 4) << 3);
                int col = ks * 16 + ((lane >> 3) & 1) * 8;
                uint32_t addr = smem_u32(&sb[n * HPAD + col]);
                uint32_t r0, r1, r2, r3;
                asm volatile("ldmatrix.sync.aligned.m8n8.x4.shared.b16 {%0,%1,%2,%3}, [%4];\n"
                             : "=r"(r0), "=r"(r1), "=r"(r2), "=r"(r3) : "r"(addr));
                b[2 * j][0] = r0; b[2 * j][1] = r1;
                b[2 * j + 1][0] = r2; b[2 * j + 1][1] = r3;
            }
#pragma unroll
            for (int mi = 0; mi < MI; mi++)
#pragma unroll
                for (int ni = 0; ni < NI; ni++)
                    asm volatile(
                        "mma.sync.aligned.m16n8k16.row.col.f32.f16.f16.f32 "
                        "{%0,%1,%2,%3}, {%4,%5,%6,%7}, {%8,%9}, {%0,%1,%2,%3};\n"
                        : "+f"(acc[mi][ni][0]), "+f"(acc[mi][ni][1]),
                          "+f"(acc[mi][ni][2]), "+f"(acc[mi][ni][3])
                        : "r"(a[mi][0]), "r"(a[mi][1]), "r"(a[mi][2]), "r"(a[mi][3]),
                          "r"(b[ni][0]), "r"(b[ni][1]));
        }
    }
    __syncthreads();

    // epilogue
    const float* bz = bias + z * sBias;
#pragma unroll
    for (int mi = 0; mi < MI; mi++) {
        int row = m0 + wr * (MI * 16) + mi * 16 + (lane >> 2);
#pragma unroll
        for (int ni = 0; ni < NI; ni++) {
            int col = n0 + wc * WTN + ni * 8 + (lane & 3) * 2;
            float2 lo = make_float2(acc[mi][ni][0] * alpha, acc[mi][ni][1] * alpha);
            float2 hi = make_float2(acc[mi][ni][2] * alpha, acc[mi][ni][3] * alpha);
            if (BIASM == 1) {
                float b0 = bz[col], b1 = bz[col + 1];
                lo.x += b0; lo.y += b1; hi.x += b0; hi.y += b1;
            }
            if (BIASM == 2) {
                float br = bz[row], br8 = bz[row + 8];
                lo.x += br; lo.y += br; hi.x += br8; hi.y += br8;
            }
            if (CADDM == 1) {
                const float* ca = CaddF + z * sAdd;
                float2 c0 = *(const float2*)&ca[(size_t)row * ldadd + col];
                float2 c1 = *(const float2*)&ca[(size_t)(row + 8) * ldadd + col];
                lo.x += c0.x; lo.y += c0.y;
                hi.x += c1.x; hi.y += c1.y;
            }
            if (CADDM == 2) {
                const __half* ca = CaddH + z * sAdd;
                float2 c0 = __half22float2(*(const __half2*)&ca[(size_t)row * ldadd + col]);
                float2 c1 = __half22float2(*(const __half2*)&ca[(size_t)(row + 8) * ldadd + col]);
                lo.x += c0.x; lo.y += c0.y;
                hi.x += c1.x; hi.y += c1.y;
            }
            if (RELU) {
                lo.x = fmaxf(lo.x, 0.f); lo.y = fmaxf(lo.y, 0.f);
                hi.x = fmaxf(hi.x, 0.f); hi.y = fmaxf(hi.y, 0.f);
            }
            if (OUTF16) {
                __half* co = Ch + z * sC;
                __half2 h2lo = __floats2half2_rn(lo.x, lo.y);
                __half2 h2hi = __floats2half2_rn(hi.x, hi.y);
                *(__half2*)&co[(size_t)row * ldc + col]       = h2lo;
                *(__half2*)&co[(size_t)(row + 8) * ldc + col] = h2hi;
                if (TROUT) {
                    __half* ct = ChT + z * sCT;
                    ct[(size_t)col * ldT + row]           = __low2half(h2lo);
                    ct[(size_t)(col + 1) * ldT + row]     = __high2half(h2lo);
                    ct[(size_t)col * ldT + row + 8]       = __low2half(h2hi);
                    ct[(size_t)(col + 1) * ldT + row + 8] = __high2half(h2hi);
                }
            } else {
                float* co = C + z * sC;
                *(float2*)&co[(size_t)row * ldc + col]       = lo;
                *(float2*)&co[(size_t)(row + 8) * ldc + col] = hi;
            }
        }
    }
}

template<int BN, int WTN, bool RELU, int CADDM, bool OUTF16, int BIASM, bool DUALA = false, bool TROUT = false>
static inline void hgemm(const __half* A, const __half* A2, int lda, long sA,
                         const __half* B, int ldb, long sB,
                         float* C, __half* Ch, int ldc, long sC,
                         const float* CaddF, const __half* CaddH, int ldadd, long sAdd,
                         const float* bias, long sBias, float alpha,
                         int Md, int Nd, int Kd, int batch,
                         __half* ChT = nullptr, int ldT = 0, long sCT = 0)
{
    constexpr int SMEM = 3 * (128 + BN) * HPAD * 2;
    cudaFuncSetAttribute(hgemm_k<BN, WTN, RELU, CADDM, OUTF16, BIASM, DUALA, TROUT>,
                         cudaFuncAttributeMaxDynamicSharedMemorySize, SMEM);
    dim3 grid(Nd / BN, Md / 128, batch);
    hgemm_k<BN, WTN, RELU, CADDM, OUTF16, BIASM, DUALA, TROUT><<<grid, 256, SMEM>>>(
        A, A2, lda, sA, B, ldb, sB, C, Ch, ldc, sC, CaddF, CaddH, ldadd, sAdd,
        bias, sBias, ChT, ldT, sCT, alpha, Md, Nd, Kd);
}

// ---------------- conversions ----------------
__global__ void __launch_bounds__(256)
conv_k(const float4* __restrict__ in, __half2* __restrict__ out, int n4)
{
    int i = blockIdx.x * 256 + threadIdx.x;
    if (i < n4) {
        float4 v = in[i];
        out[2 * i]     = __floats2half2_rn(v.x, v.y);
        out[2 * i + 1] = __floats2half2_rn(v.z, v.w);
    }
}

// batched transpose of nine 512x512 f32 weights -> packed fp16 [N][K] slots
struct WPtr9 { const float* s[9]; };
__global__ void __launch_bounds__(256)
tconv9_k(WPtr9 w, __half* __restrict__ out)
{
    __shared__ float t[32][33];
    const float* in = w.s[blockIdx.z];
    __half* o = out + (size_t)blockIdx.z * WSQ;
    int c0 = blockIdx.x * 32, r0 = blockIdx.y * 32;
    int x = threadIdx.x & 31, y = threadIdx.x >> 5;
#pragma unroll
    for (int j = 0; j < 32; j += 8)
        t[y + j][x] = in[(size_t)(r0 + y + j) * HID + c0 + x];
    __syncthreads();
#pragma unroll
    for (int j = 0; j < 32; j += 8)
        o[(size_t)(c0 + y + j) * HID + r0 + x] = __float2half(t[x][y + j]);
}

// batched transpose of the two [1024,256] f32 final weights -> [256][1024] fp16
struct WPtr2 { const float* s[2]; __half* d[2]; };
__global__ void __launch_bounds__(256)
tconv2_k(WPtr2 w)
{
    __shared__ float t[32][33];
    const float* in = w.s[blockIdx.z];
    __half* o = w.d[blockIdx.z];
    int c0 = blockIdx.x * 32, r0 = blockIdx.y * 32;
    int x = threadIdx.x & 31, y = threadIdx.x >> 5;
#pragma unroll
    for (int j = 0; j < 32; j += 8)
        t[y + j][x] = in[(size_t)(r0 + y + j) * DHALF + c0 + x];
    __syncthreads();
#pragma unroll
    for (int j = 0; j < 32; j += 8)
        o[(size_t)(c0 + y + j) * (2 * HID) + r0 + x] = __float2half(t[x][y + j]);
}

// pack 9 bias vectors (512 each) into one contiguous buffer
__global__ void __launch_bounds__(512)
pack_bias_k(float* __restrict__ dst,
            const float* b0, const float* b1, const float* b2,
            const float* b3, const float* b4, const float* b5,
            const float* b6, const float* b7, const float* b8)
{
    int t = threadIdx.x;
    dst[0 * HID + t] = b0[t];
    dst[1 * HID + t] = b1[t];
    dst[2 * HID + t] = b2[t];
    dst[3 * HID + t] = b3[t];
    dst[4 * HID + t] = b4[t];
    dst[5 * HID + t] = b5[t];
    dst[6 * HID + t] = b6[t];
    dst[7 * HID + t] = b7[t];
    dst[8 * HID + t] = b8[t];
}

// ---------------- reductions ----------------
__device__ __forceinline__ float warpRedMax(float v) {
#pragma unroll
    for (int o = 16; o > 0; o >>= 1) v = fmaxf(v, __shfl_xor_sync(0xffffffffu, v, o));
    return v;
}
__device__ __forceinline__ float warpRedSum(float v) {
#pragma unroll
    for (int o = 16; o > 0; o >>= 1) v += __shfl_xor_sync(0xffffffffu, v, o);
    return v;
}
__device__ __forceinline__ float blockSum256(float v, float* red) {
    int lane = threadIdx.x & 31, w = threadIdx.x >> 5;
    v = warpRedSum(v);
    if (lane == 0) red[w] = v;
    __syncthreads();
    float r = 0.f;
#pragma unroll
    for (int i = 0; i < 8; i++) r += red[i];
    __syncthreads();
    return r;
}

// ---------------- fused masked softmax + transpose (fp16) ----------------
// Block: 32 rows (l) x 1024 (m) of head h. Normalizes in place into S and
// writes the transpose into ST[(h*M + m) * R + l].
#define SMT_PITCH 1026
#define SMT_BYTES (32 * SMT_PITCH * 2)

__global__ void __launch_bounds__(256)
softmaxT_k(__half* __restrict__ S, __half* __restrict__ ST,
           const int* __restrict__ mask, int R)
{
    extern __shared__ __half sm[];
    const int h  = blockIdx.y;
    const int l0 = blockIdx.x * 32;
    const int wid = threadIdx.x >> 5, lane = threadIdx.x & 31;

#pragma unroll 1
    for (int rr = 0; rr < 4; rr++) {
        const int row = rr * 8 + wid;
        const int l = l0 + row;
        const __half2* src = (const __half2*)(S + (size_t)l * HK + (size_t)h * M_DIM);
        const int2*    m2  = (const int2*)(mask + (size_t)l * M_DIM);

        float2 v[16];
        float mx = -3.4e38f;
#pragma unroll
        for (int i = 0; i < 16; i++) {
            float2 f = __half22float2(src[lane + i * 32]);
            int2  mm = m2[lane + i * 32];
            f.x = (mm.x != 0) ? f.x : -1e9f;
            f.y = (mm.y != 0) ? f.y : -1e9f;
            v[i] = f;
            mx = fmaxf(mx, fmaxf(f.x, f.y));
        }
        mx = warpRedMax(mx);
        float sum = 0.f;
#pragma unroll
        for (int i = 0; i < 16; i++) {
            v[i].x = __expf(v[i].x - mx);
            v[i].y = __expf(v[i].y - mx);
            sum += v[i].x + v[i].y;
        }
        sum = warpRedSum(sum);
        float inv = __frcp_rn(sum);

        __half2* srow = (__half2*)(sm + row * SMT_PITCH);
#pragma unroll
        for (int i = 0; i < 16; i++)
            srow[lane + i * 32] = __floats2half2_rn(v[i].x * inv, v[i].y * inv);
    }
    __syncthreads();

    for (int idx = threadIdx.x; idx < 32 * 512; idx += 256) {
        int row = idx >> 9, c2 = idx & 511;
        __half2 hv = ((const __half2*)(sm + row * SMT_PITCH))[c2];
        ((__half2*)(S + (size_t)(l0 + row) * HK + (size_t)h * M_DIM))[c2] = hv;
    }
    for (int idx = threadIdx.x; idx < 1024 * 16; idx += 256) {
        int m = idx >> 4, lp = idx & 15;
        __half a = sm[(2 * lp)     * SMT_PITCH + m];
        __half b = sm[(2 * lp + 1) * SMT_PITCH + m];
        ((__half2*)(ST + (size_t)(h * M_DIM + m) * R + l0))[lp] = __halves2half2(a, b);
    }
}

// ---------------- layernorm ----------------
__global__ void __launch_bounds__(256)
ln_k(const float* __restrict__ x, const float* __restrict__ g, const float* __restrict__ be,
     float* __restrict__ out)
{
    __shared__ float red[8];
    const int r = blockIdx.x, t = threadIdx.x;
    float v = x[r * 256 + t];
    float mean = blockSum256(v, red) * (1.f / 256.f);
    float d = v - mean;
    float var = blockSum256(d * d, red) * (1.f / 256.f);
    out[r * 256 + t] = d * rsqrtf(var + EPS_LN) * g[t] + be[t];
}

// ---------------- launch ----------------
static inline void* symraw(const void* s) {
    void* p = nullptr;
    cudaGetSymbolAddress(&p, s);
    return p;
}

extern "C" void kernel_launch(void* const* d_in, const int* in_sizes, int n_in,
                              void* d_out, int out_size)
{
    (void)in_sizes; (void)n_in; (void)out_size;
    const float* Le    = (const float*)d_in[0];
    const float* Me    = (const float*)d_in[1];
    const float* Pe    = (const float*)d_in[2];
    const int*   maskL = (const int*)  d_in[3];
    const int*   maskP = (const int*)  d_in[4];
    const float *Wl  = (const float*)d_in[5],  *bl  = (const float*)d_in[6];
    const float *Wm  = (const float*)d_in[7],  *bm  = (const float*)d_in[8];
    const float *Wp  = (const float*)d_in[9],  *bp  = (const float*)d_in[10];
    const float *Wql = (const float*)d_in[11], *bql = (const float*)d_in[12];
    const float *Wkl = (const float*)d_in[13], *bkl = (const float*)d_in[14];
    const float *Wvl = (const float*)d_in[15], *bvl = (const float*)d_in[16];
    const float *Wqp = (const float*)d_in[17], *bqp = (const float*)d_in[18];
    const float *Wkp = (const float*)d_in[19], *bkp = (const float*)d_in[20];
    const float *Wvp = (const float*)d_in[21], *bvp = (const float*)d_in[22];
    const float *Wml = (const float*)d_in[23], *bml = (const float*)d_in[24];
    const float *Wmp = (const float*)d_in[25], *bmp = (const float*)d_in[26];
    const float *g1  = (const float*)d_in[27], *be1 = (const float*)d_in[28];
    const float *g2  = (const float*)d_in[29], *be2 = (const float*)d_in[30];

    float* preL = (float*)symraw(g_preL);
    float* preP = (float*)symraw(g_preP);

    __half* hWcat  = (__half*)symraw(g_hWcat);
    float*  biascat= (float*) symraw(g_biascat);
    __half* hWmlT  = (__half*)symraw(g_hWmlT);
    __half* hWmpT  = (__half*)symraw(g_hWmpT);

    __half* hEmb  = (__half*)symraw(g_hEmb);
    __half* hMe   = (__half*)symraw(g_hMe);
    __half* hmt   = (__half*)symraw(g_hmt);
    __half* hltpt = (__half*)symraw(g_hltpt);
    __half* hQlp  = (__half*)symraw(g_hQlp);
    __half* hKm   = (__half*)symraw(g_hKm);
    __half* hVTm  = (__half*)symraw(g_hVTm);
    __half* haw   = (__half*)symraw(g_haw);
    __half* hawT  = (__half*)symraw(g_hawT);
    __half* hctx  = (__half*)symraw(g_hctx);
    __half* hctxT = (__half*)symraw(g_hctxT);
    __half* hTT   = (__half*)symraw(g_hTT);
    __half* hfin  = (__half*)symraw(g_hfin);

    const float scale = 0.125f;   // 1/sqrt(DH)
    const float invH  = 0.125f;   // 1/H

    const long ES = (long)L_DIM * HID;     // embedding-sized stride
    const long AS = (long)L_DIM * HK;      // attention-map stride

    // 0) inputs + weights -> fp16 (weights transposed to [N][K], packed/batched)
    conv_k<<<(L_DIM * HID / 4 + 255) / 256, 256>>>((const float4*)Le, (__half2*)hEmb, L_DIM * HID / 4);
    conv_k<<<(P_DIM * HID / 4 + 255) / 256, 256>>>((const float4*)Pe, (__half2*)(hEmb + ES), P_DIM * HID / 4);
    conv_k<<<(M_DIM * HID / 4 + 255) / 256, 256>>>((const float4*)Me, (__half2*)hMe, M_DIM * HID / 4);
    {
        WPtr9 w9;
        w9.s[0] = Wl;  w9.s[1] = Wp;  w9.s[2] = Wm;
        w9.s[3] = Wql; w9.s[4] = Wqp; w9.s[5] = Wkl;
        w9.s[6] = Wkp; w9.s[7] = Wvl; w9.s[8] = Wvp;
        tconv9_k<<<dim3(HID / 32, HID / 32, 9), 256>>>(w9, hWcat);
        WPtr2 w2;
        w2.s[0] = Wml; w2.s[1] = Wmp;
        w2.d[0] = hWmlT; w2.d[1] = hWmpT;
        tconv2_k<<<dim3(DHALF / 32, 2 * HID / 32, 2), 256>>>(w2);
    }
    pack_bias_k<<<1, 512>>>(biascat, bl, bp, bm, bql, bqp, bkl, bkp, bvl, bvp);

    // 1) {Le,Pe} @ {Wl,Wp} -> {lt,pt}   (z=2)
    hgemm<128,32,false,0,true,1>(hEmb, nullptr, HID, ES, hWcat, HID, WSQ,
                                 nullptr, hltpt, HID, ES, nullptr, nullptr, 0, 0,
                                 biascat, HID, 1.f, L_DIM, HID, HID, 2);
    // 2) Me @ Wm -> mt
    hgemm<128,32,false,0,true,1>(hMe, nullptr, HID, 0, hWcat + 2 * WSQ, HID, 0,
                                 nullptr, hmt, HID, 0, nullptr, nullptr, 0, 0,
                                 biascat + 2 * HID, 0, 1.f, M_DIM, HID, HID, 1);
    // 3) {lt,pt} @ {Wql,Wqp} -> {Ql,Qp}  (z=2)
    hgemm<128,32,false,0,true,1>(hltpt, nullptr, HID, ES, hWcat + 3 * WSQ, HID, WSQ,
                                 nullptr, hQlp, HID, ES, nullptr, nullptr, 0, 0,
                                 biascat + 3 * HID, HID, 1.f, L_DIM, HID, HID, 2);
    // 4) mt @ {Wkl,Wkp} -> {Kl,Kp}       (z=2, A shared)
    hgemm<128,32,false,0,true,1>(hmt, nullptr, HID, 0, hWcat + 5 * WSQ, HID, WSQ,
                                 nullptr, hKm, HID, (long)M_DIM * HID, nullptr, nullptr, 0, 0,
                                 biascat + 5 * HID, HID, 1.f, M_DIM, HID, HID, 2);
    // 5) {Wvl,Wvp}^T-trick: V^T = W^T @ mt^T  (z=2, row bias)
    hgemm<128,32,false,0,true,2>(hWcat + 7 * WSQ, nullptr, HID, WSQ, hmt, HID, 0,
                                 nullptr, hVTm, M_DIM, (long)HID * M_DIM, nullptr, nullptr, 0, 0,
                                 biascat + 7 * HID, HID, 1.f, HID, M_DIM, HID, 2);

    // 6) attention scores (z=8 heads) -> fp16 score buffers
    hgemm<128,32,false,0,true,0>(hQlp, nullptr, HID, DH, hKm, HID, DH,
                                 nullptr, haw, HK, M_DIM, nullptr, nullptr, 0, 0,
                                 nullptr, 0, scale, L_DIM, M_DIM, DH, NH);
    hgemm<128,32,false,0,true,0>(hQlp + ES, nullptr, HID, DH, hKm + (long)M_DIM * HID, HID, DH,
                                 nullptr, haw + AS, HK, M_DIM, nullptr, nullptr, 0, 0,
                                 nullptr, 0, scale, P_DIM, M_DIM, DH, NH);

    // 7) fused masked softmax + aw transpose (p-first layout in hawT)
    cudaFuncSetAttribute(softmaxT_k, cudaFuncAttributeMaxDynamicSharedMemorySize, SMT_BYTES);
    softmaxT_k<<<dim3(L_DIM / 32, NH), 256, SMT_BYTES>>>(haw, hawT + (size_t)HK * L_DIM, maskL, L_DIM);
    softmaxT_k<<<dim3(P_DIM / 32, NH), 256, SMT_BYTES>>>(haw + AS, hawT, maskP, P_DIM);

    // 8) context (BN=64, NT vs V^T, relu) -> fp16 ctx + fused transposed output
    hgemm<64,32,true,0,true,0,false,true>(
        haw, nullptr, HK, M_DIM, hVTm, M_DIM, (long)DH * M_DIM,
        nullptr, hctx, HID, DH, nullptr, nullptr, 0, 0,
        nullptr, 0, 1.f, L_DIM, DH, M_DIM, NH,
        hctxT + (long)HID * L_DIM, L_DIM, (long)DH * L_DIM);
    hgemm<64,32,true,0,true,0,false,true>(
        haw + AS, nullptr, HK, M_DIM, hVTm + (long)HID * M_DIM, M_DIM, (long)DH * M_DIM,
        nullptr, hctx + ES, HID, DH, nullptr, nullptr, 0, 0,
        nullptr, 0, 1.f, P_DIM, DH, M_DIM, NH,
        hctxT, P_DIM, (long)DH * P_DIM);

    // 9) T-GEMMs batched (z=2): TpT = ctxp^T @ awp ; TlT = ctxl^T @ awl
    hgemm<128,32,false,0,true,0>(hctxT, nullptr, P_DIM, (long)HID * P_DIM, hawT, P_DIM, (long)HK * P_DIM,
                                 nullptr, hTT, HK, (long)HID * HK, nullptr, nullptr, 0, 0,
                                 nullptr, 0, 1.f, HID, HK, P_DIM, 2);
    // 10) fin batched (z=2): finl = ctxl + (1/H) awl @ TpT^T ; finp = ctxp + (1/H) awp @ TlT^T
    hgemm<128,32,false,2,true,0>(haw, nullptr, HK, AS, hTT, HK, (long)HID * HK,
                                 nullptr, hfin, HID, ES, nullptr, hctx, HID, ES,
                                 nullptr, 0, invH, L_DIM, HID, HK, 2);

    // 11) final linears: single K=1024 GEMM each via dual-A (concat semantics)
    hgemm<64,32,false,0,false,1,true>(hltpt, hfin, HID, 0, hWmlT, 2 * HID, 0,
                                      preL, nullptr, DHALF, 0, nullptr, nullptr, 0, 0,
                                      bml, 0, 1.f, L_DIM, DHALF, 2 * HID, 1);
    hgemm<64,32,false,0,false,1,true>(hfin + ES, hltpt + ES, HID, 0, hWmpT, 2 * HID, 0,
                                      preP, nullptr, DHALF, 0, nullptr, nullptr, 0, 0,
                                      bmp, 0, 1.f, P_DIM, DHALF, 2 * HID, 1);

    // 12) layernorms -> output
    float* out = (float*)d_out;
    ln_k<<<L_DIM, 256>>>(preL, g1, be1, out);
    ln_k<<<P_DIM, 256>>>(preP, g2, be2, out + (size_t)L_DIM * DHALF);
}